// round 13
// baseline (speedup 1.0000x reference)
#include <cuda_runtime.h>
#include <cuda_bf16.h>
#include <cuda_fp16.h>
#include <math.h>
#include <stdint.h>

// Problem dims (fixed)
#define BB 4
#define SS 2048
#define DD 1024
#define MS (BB*SS)          // 8192 rows total
#define OUT_ELEMS (MS*DD)

// --- bf16 split GEMM smem geometry: rows hold hi(64B)|lo(64B), stride 144B ---
#define ROWB   144
#define ATILEB (128*ROWB)
#define STAGEB (2*ATILEB)              // A + B tile = 36864 B
#define NSTAGE 3
#define SMEMB  (NSTAGE*STAGEB)         // 110592 B

// int8 quant constants: fixed 8-sigma scales for x and Wv (x~N(0,1), Wv~N(0,1)/32)
#define QX_RANGE 8.0f
#define QW_RANGE 0.25f
#define QMAX 32512.0f       // 127*256 + 127... = full int8-pair span

// ---------------------------------------------------------------------------
// PTX helpers (sm_80-level only: cp.async, ldmatrix, mma.sync)
// ---------------------------------------------------------------------------
__device__ __forceinline__ uint32_t smem_u32(const void* p) {
    uint32_t a;
    asm("{ .reg .u64 t; cvta.to.shared.u64 t, %1; cvt.u32.u64 %0, t; }" : "=r"(a) : "l"(p));
    return a;
}
#define CP16(d, s) asm volatile("cp.async.cg.shared.global [%0], [%1], 16;" :: "r"(d), "l"(s))
#define CPCOMMIT() asm volatile("cp.async.commit_group;" ::: "memory")
#define CPWAIT(n)  asm volatile("cp.async.wait_group %0;" :: "n"(n) : "memory")

__device__ __forceinline__ void ldsm4(uint32_t* r, uint32_t a) {
    asm volatile("ldmatrix.sync.aligned.m8n8.x4.shared.b16 {%0,%1,%2,%3}, [%4];"
                 : "=r"(r[0]), "=r"(r[1]), "=r"(r[2]), "=r"(r[3]) : "r"(a));
}
__device__ __forceinline__ void mma16816(float* c, const uint32_t* a, const uint32_t* b) {
    asm volatile("mma.sync.aligned.m16n8k16.row.col.f32.bf16.bf16.f32 "
                 "{%0,%1,%2,%3}, {%4,%5,%6,%7}, {%8,%9}, {%0,%1,%2,%3};"
                 : "+f"(c[0]), "+f"(c[1]), "+f"(c[2]), "+f"(c[3])
                 : "r"(a[0]), "r"(a[1]), "r"(a[2]), "r"(a[3]), "r"(b[0]), "r"(b[1]));
}
__device__ __forceinline__ void mma16832i(int* c, const uint32_t* a, const uint32_t* b) {
    asm volatile("mma.sync.aligned.m16n8k32.row.col.s32.s8.s8.s32 "
                 "{%0,%1,%2,%3}, {%4,%5,%6,%7}, {%8,%9}, {%0,%1,%2,%3};"
                 : "+r"(c[0]), "+r"(c[1]), "+r"(c[2]), "+r"(c[3])
                 : "r"(a[0]), "r"(a[1]), "r"(a[2]), "r"(a[3]), "r"(b[0]), "r"(b[1]));
}

// quantize |t| <= QMAX into int8 pair: t ~= 256*hi + lo
__device__ __forceinline__ void quant_pair(float t, int8_t& hi, int8_t& lo) {
    float h = rintf(t * 0.00390625f);                 // /256
    float l = rintf(t - 256.f * h);
    l = fminf(127.f, fmaxf(-127.f, l));
    hi = (int8_t)h; lo = (int8_t)l;
}

// ---------------------------------------------------------------------------
// Static scratch (allocation-free rule)
// ---------------------------------------------------------------------------
__device__ __align__(256) __nv_bfloat16 g_xh[MS*DD], g_xl[MS*DD];
__device__ __align__(256) __nv_bfloat16 g_wqh[DD*DD], g_wql[DD*DD];
__device__ __align__(256) __nv_bfloat16 g_wkh[DD*DD], g_wkl[DD*DD];
__device__ __align__(256) float          g_mtp[4*DD*DD];
__device__ __align__(256) __nv_bfloat16 g_mth[DD*DD], g_mtl[DD*DD];     // M^T = Wk Wq^T
__device__ __align__(256) __nv_bfloat16 g_yh[MS*DD], g_yl[MS*DD];       // y = x M
__device__ __align__(256) float          g_p[(size_t)BB*SS*SS];
__device__ __align__(256) int8_t         g_p8h[(size_t)BB*SS*SS], g_p8l[(size_t)BB*SS*SS];
__device__ __align__(256) float          g_sp[MS];
__device__ __align__(256) int8_t         g_xt8h[MS*DD], g_xt8l[MS*DD];  // x^T per batch [D,S]
__device__ __align__(256) int8_t         g_wvt8h[DD*DD], g_wvt8l[DD*DD];// Wv^T [j,d]
__device__ __align__(256) float          g_z[MS*DD];                     // z fp32
__device__ __align__(256) int8_t         g_z8h[MS*DD], g_z8l[MS*DD];
__device__ __align__(256) float          g_sz[MS];
__device__ __align__(256) float          g_cq[DD], g_ck[DD], g_u[MS], g_w[MS], g_s0[1];
__device__ __align__(256) float          g_ent[MS];

// ---------------------------------------------------------------------------
// bf16 split GEMM via mma.sync (R10 proven config):
//   C[M,N] = (Ah+Al)[.,K] x (Bh+Bl)[.,K]^T   (3 MMAs: hh + hl + lh)
// CTA tile 128x128, K-chunk 32, 256 threads = 8 warps (4 M x 2 N),
// 3-stage cp.async ring, ONE barrier/chunk, 2 CTAs/SM.
// EPI 0: fp32 store.  EPI 2: bf16 hi/lo split store.
// ---------------------------------------------------------------------------
template<int EPI>
__global__ __launch_bounds__(256, 2)
void mma_gemm(const __nv_bfloat16* __restrict__ Ah, const __nv_bfloat16* __restrict__ Al,
              const __nv_bfloat16* __restrict__ Bh, const __nv_bfloat16* __restrict__ Bl,
              float* __restrict__ Cf, __nv_bfloat16* __restrict__ Oh, __nv_bfloat16* __restrict__ Ol,
              int N, int K, int lda, int ldb, long sA, long sB, long sC)
{
    extern __shared__ char sm[];
    const uint32_t sb = smem_u32(sm);
    const int tid = threadIdx.x, lane = tid & 31, warp = tid >> 5;
    const int wm = warp & 3, wn = warp >> 2;     // 4 M-warps x 2 N-warps
    const int bz = blockIdx.z;

    const __nv_bfloat16* srcA[2] = {
        Ah + (long)bz * sA + (long)blockIdx.y * 128 * lda,
        Al + (long)bz * sA + (long)blockIdx.y * 128 * lda };
    const __nv_bfloat16* srcB[2] = {
        Bh + (long)bz * sB + (long)blockIdx.x * 128 * ldb,
        Bl + (long)bz * sB + (long)blockIdx.x * 128 * ldb };

    float acc[2][8][4];
    #pragma unroll
    for (int a = 0; a < 2; a++)
        #pragma unroll
        for (int b = 0; b < 8; b++)
            #pragma unroll
            for (int c = 0; c < 4; c++) acc[a][b][c] = 0.f;

    const int NC = K >> 5;

    auto load_stage = [&](int c) {
        const uint32_t dstS = sb + (uint32_t)(c % NSTAGE) * STAGEB;
        const long kof = (long)c * 32;
        #pragma unroll
        for (int p = 0; p < 4; p++) {
            const int u = tid + p * 256;
            const int r = u >> 3, seg = u & 7;
            const int hl = seg >> 2;
            const long so = kof + (seg & 3) * 8;
            CP16(dstS + r * ROWB + seg * 16,          srcA[hl] + (long)r * lda + so);
            CP16(dstS + ATILEB + r * ROWB + seg * 16, srcB[hl] + (long)r * ldb + so);
        }
        CPCOMMIT();
    };

    load_stage(0);
    if (NC > 1) load_stage(1);

    for (int c = 0; c < NC; c++) {
        if (c + 2 <= NC) { CPWAIT(1); } else { CPWAIT(0); }
        __syncthreads();
        if (c + 2 < NC) load_stage(c + 2);

        const uint32_t stb = sb + (uint32_t)(c % NSTAGE) * STAGEB;
        #pragma unroll
        for (int ks = 0; ks < 2; ks++) {
            uint32_t aHi[2][4], aLo[2][4];
            const int rA   = wm * 32 + (lane & 15);
            const int colA = ks * 32 + ((lane >> 4) << 4);
            #pragma unroll
            for (int mf = 0; mf < 2; mf++) {
                const uint32_t ad = stb + (rA + mf * 16) * ROWB + colA;
                ldsm4(aHi[mf], ad);
                ldsm4(aLo[mf], ad + 64);
            }
            const int rB   = wn * 64 + ((lane >> 4) & 1) * 8 + (lane & 7);
            const int colB = ks * 32 + ((lane >> 3) & 1) * 16;
            #pragma unroll
            for (int g = 0; g < 4; g++) {
                uint32_t bh4[4], bl4[4];
                const uint32_t bd = stb + ATILEB + (rB + g * 16) * ROWB + colB;
                ldsm4(bh4, bd);
                ldsm4(bl4, bd + 64);
                #pragma unroll
                for (int mf = 0; mf < 2; mf++) {
                    mma16816(acc[mf][2*g],   aHi[mf], bh4);
                    mma16816(acc[mf][2*g],   aHi[mf], bl4);
                    mma16816(acc[mf][2*g],   aLo[mf], bh4);
                    mma16816(acc[mf][2*g+1], aHi[mf], bh4 + 2);
                    mma16816(acc[mf][2*g+1], aHi[mf], bl4 + 2);
                    mma16816(acc[mf][2*g+1], aLo[mf], bh4 + 2);
                }
            }
        }
    }

    const long rbase = (long)blockIdx.y * 128 + wm * 32 + (lane >> 2);
    const int  gcol0 = blockIdx.x * 128;

    #pragma unroll
    for (int mf = 0; mf < 2; mf++)
        #pragma unroll
        for (int rh = 0; rh < 2; rh++) {
            const long r = rbase + mf * 16 + rh * 8;
            #pragma unroll
            for (int nf = 0; nf < 8; nf++) {
                const int col = gcol0 + wn * 64 + 2 * (lane & 3) + nf * 8;
                float v0 = acc[mf][nf][rh * 2 + 0];
                float v1 = acc[mf][nf][rh * 2 + 1];
                if (EPI == 0) {
                    float2 f2; f2.x = v0; f2.y = v1;
                    *(float2*)(Cf + (long)bz * sC + r * N + col) = f2;
                } else {
                    __nv_bfloat16 h0 = __float2bfloat16(v0);
                    __nv_bfloat16 h1 = __float2bfloat16(v1);
                    __nv_bfloat162 hh; hh.x = h0; hh.y = h1;
                    __nv_bfloat162 ll;
                    ll.x = __float2bfloat16(v0 - __bfloat162float(h0));
                    ll.y = __float2bfloat16(v1 - __bfloat162float(h1));
                    *(__nv_bfloat162*)(Oh + (long)bz * sC + r * N + col) = hh;
                    *(__nv_bfloat162*)(Ol + (long)bz * sC + r * N + col) = ll;
                }
            }
        }
}

// ---------------------------------------------------------------------------
// int8-pair IMMA GEMM: C = (256*Ah+Al) x (256*Bh+Bl)^T scaled.
//   3 MMAs: hh -> accA, hl+lh -> accB; val = sA[r]*sB*(65536*accA + 256*accB)
// CTA tile 128x128, K-chunk 64 (2 x k32), 256 threads, 8 warps (4M x 2N),
// 3-stage ring, 1 CTA/SM (2 int32 acc sets ~ 190 regs).
// EPI 0: fp32 store (z). EPI 1: fp32 + bias (out).
// ---------------------------------------------------------------------------
template<int EPI>
__global__ __launch_bounds__(256, 1)
void mma_gemm_i8(const int8_t* __restrict__ A8h, const int8_t* __restrict__ A8l,
                 const int8_t* __restrict__ B8h, const int8_t* __restrict__ B8l,
                 const float* __restrict__ sA, long sSA, float sB,
                 const float* __restrict__ bias, float* __restrict__ Cf,
                 int N, int K, int lda, int ldb, long strA, long strB, long strC)
{
    extern __shared__ char sm[];
    const uint32_t sb = smem_u32(sm);
    const int tid = threadIdx.x, lane = tid & 31, warp = tid >> 5;
    const int wm = warp & 3, wn = warp >> 2;
    const int bz = blockIdx.z;

    const int8_t* srcA[2] = {
        A8h + (long)bz * strA + (long)blockIdx.y * 128 * lda,
        A8l + (long)bz * strA + (long)blockIdx.y * 128 * lda };
    const int8_t* srcB[2] = {
        B8h + (long)bz * strB + (long)blockIdx.x * 128 * ldb,
        B8l + (long)bz * strB + (long)blockIdx.x * 128 * ldb };

    int accA[2][8][4], accB[2][8][4];
    #pragma unroll
    for (int a = 0; a < 2; a++)
        #pragma unroll
        for (int b = 0; b < 8; b++)
            #pragma unroll
            for (int c = 0; c < 4; c++) { accA[a][b][c] = 0; accB[a][b][c] = 0; }

    const int NC = K >> 6;            // chunk K=64 int8

    auto load_stage = [&](int c) {
        const uint32_t dstS = sb + (uint32_t)(c % NSTAGE) * STAGEB;
        const long kof = (long)c * 64;
        #pragma unroll
        for (int p = 0; p < 4; p++) {
            const int u = tid + p * 256;
            const int r = u >> 3, seg = u & 7;
            const int hl = seg >> 2;
            const long so = kof + (seg & 3) * 16;
            CP16(dstS + r * ROWB + seg * 16,          srcA[hl] + (long)r * lda + so);
            CP16(dstS + ATILEB + r * ROWB + seg * 16, srcB[hl] + (long)r * ldb + so);
        }
        CPCOMMIT();
    };

    load_stage(0);
    if (NC > 1) load_stage(1);

    for (int c = 0; c < NC; c++) {
        if (c + 2 <= NC) { CPWAIT(1); } else { CPWAIT(0); }
        __syncthreads();
        if (c + 2 < NC) load_stage(c + 2);

        const uint32_t stb = sb + (uint32_t)(c % NSTAGE) * STAGEB;
        #pragma unroll
        for (int ks = 0; ks < 2; ks++) {          // 2 x k32
            uint32_t aHi[2][4], aLo[2][4];
            const int rA   = wm * 32 + (lane & 15);
            const int colA = ks * 32 + ((lane >> 4) << 4);
            #pragma unroll
            for (int mf = 0; mf < 2; mf++) {
                const uint32_t ad = stb + (rA + mf * 16) * ROWB + colA;
                ldsm4(aHi[mf], ad);
                ldsm4(aLo[mf], ad + 64);
            }
            const int rB   = wn * 64 + ((lane >> 4) & 1) * 8 + (lane & 7);
            const int colB = ks * 32 + ((lane >> 3) & 1) * 16;
            #pragma unroll
            for (int g = 0; g < 4; g++) {
                uint32_t bh4[4], bl4[4];
                const uint32_t bd = stb + ATILEB + (rB + g * 16) * ROWB + colB;
                ldsm4(bh4, bd);
                ldsm4(bl4, bd + 64);
                #pragma unroll
                for (int mf = 0; mf < 2; mf++) {
                    mma16832i(accA[mf][2*g],   aHi[mf], bh4);
                    mma16832i(accB[mf][2*g],   aHi[mf], bl4);
                    mma16832i(accB[mf][2*g],   aLo[mf], bh4);
                    mma16832i(accA[mf][2*g+1], aHi[mf], bh4 + 2);
                    mma16832i(accB[mf][2*g+1], aHi[mf], bl4 + 2);
                    mma16832i(accB[mf][2*g+1], aLo[mf], bh4 + 2);
                }
            }
        }
    }

    const long rbase = (long)blockIdx.y * 128 + wm * 32 + (lane >> 2);
    const int  gcol0 = blockIdx.x * 128;
    const float* sa = sA + bz * sSA;

    #pragma unroll
    for (int mf = 0; mf < 2; mf++)
        #pragma unroll
        for (int rh = 0; rh < 2; rh++) {
            const long r = rbase + mf * 16 + rh * 8;
            const float sr = sa[r] * sB;
            #pragma unroll
            for (int nf = 0; nf < 8; nf++) {
                const int col = gcol0 + wn * 64 + 2 * (lane & 3) + nf * 8;
                float v0 = sr * (65536.f * (float)accA[mf][nf][rh*2+0] + 256.f * (float)accB[mf][nf][rh*2+0]);
                float v1 = sr * (65536.f * (float)accA[mf][nf][rh*2+1] + 256.f * (float)accB[mf][nf][rh*2+1]);
                if (EPI == 1) { v0 += bias[col]; v1 += bias[col + 1]; }
                float2 f2; f2.x = v0; f2.y = v1;
                *(float2*)(Cf + (long)bz * strC + r * N + col) = f2;
            }
        }
}

// ---------------------------------------------------------------------------
// x -> bf16 hi/lo (float4 vectorized)
// ---------------------------------------------------------------------------
__global__ void split_x_kernel(const float* __restrict__ in, __nv_bfloat16* __restrict__ oh,
                               __nv_bfloat16* __restrict__ ol, int n4)
{
    int i = blockIdx.x * 256 + threadIdx.x;
    if (i < n4) {
        float4 v = ((const float4*)in)[i];
        __nv_bfloat16 h0 = __float2bfloat16(v.x), h1 = __float2bfloat16(v.y);
        __nv_bfloat16 h2 = __float2bfloat16(v.z), h3 = __float2bfloat16(v.w);
        __nv_bfloat162 hA; hA.x = h0; hA.y = h1;
        __nv_bfloat162 hB; hB.x = h2; hB.y = h3;
        __nv_bfloat162 lA, lB;
        lA.x = __float2bfloat16(v.x - __bfloat162float(h0));
        lA.y = __float2bfloat16(v.y - __bfloat162float(h1));
        lB.x = __float2bfloat16(v.z - __bfloat162float(h2));
        lB.y = __float2bfloat16(v.w - __bfloat162float(h3));
        ((__nv_bfloat162*)oh)[2*i]   = hA;
        ((__nv_bfloat162*)oh)[2*i+1] = hB;
        ((__nv_bfloat162*)ol)[2*i]   = lA;
        ((__nv_bfloat162*)ol)[2*i+1] = lB;
    }
}

__global__ void split_kernel(const float* __restrict__ in, __nv_bfloat16* __restrict__ oh,
                             __nv_bfloat16* __restrict__ ol, int n4)
{
    int i = blockIdx.x * 256 + threadIdx.x;
    if (i < n4) {
        float4 v = ((const float4*)in)[i];
        __nv_bfloat16 h0 = __float2bfloat16(v.x), h1 = __float2bfloat16(v.y);
        __nv_bfloat16 h2 = __float2bfloat16(v.z), h3 = __float2bfloat16(v.w);
        __nv_bfloat162 hA; hA.x = h0; hA.y = h1;
        __nv_bfloat162 hB; hB.x = h2; hB.y = h3;
        __nv_bfloat162 lA, lB;
        lA.x = __float2bfloat16(v.x - __bfloat162float(h0));
        lA.y = __float2bfloat16(v.y - __bfloat162float(h1));
        lB.x = __float2bfloat16(v.z - __bfloat162float(h2));
        lB.y = __float2bfloat16(v.w - __bfloat162float(h3));
        ((__nv_bfloat162*)oh)[2*i]   = hA;
        ((__nv_bfloat162*)oh)[2*i+1] = hB;
        ((__nv_bfloat162*)ol)[2*i]   = lA;
        ((__nv_bfloat162*)ol)[2*i+1] = lB;
    }
}

// MT partials (4) -> sum -> bf16 hi/lo
__global__ void mt_reduce_split(const float* __restrict__ parts, __nv_bfloat16* __restrict__ oh,
                                __nv_bfloat16* __restrict__ ol, int n4)
{
    int i = blockIdx.x * 256 + threadIdx.x;
    if (i < n4) {
        float4 s = ((const float4*)parts)[i];
        #pragma unroll
        for (int p = 1; p < 4; p++) {
            float4 t = ((const float4*)(parts + (size_t)p * DD * DD))[i];
            s.x += t.x; s.y += t.y; s.z += t.z; s.w += t.w;
        }
        __nv_bfloat16 h0 = __float2bfloat16(s.x), h1 = __float2bfloat16(s.y);
        __nv_bfloat16 h2 = __float2bfloat16(s.z), h3 = __float2bfloat16(s.w);
        __nv_bfloat162 hA; hA.x = h0; hA.y = h1;
        __nv_bfloat162 hB; hB.x = h2; hB.y = h3;
        __nv_bfloat162 lA, lB;
        lA.x = __float2bfloat16(s.x - __bfloat162float(h0));
        lA.y = __float2bfloat16(s.y - __bfloat162float(h1));
        lB.x = __float2bfloat16(s.z - __bfloat162float(h2));
        lB.y = __float2bfloat16(s.w - __bfloat162float(h3));
        ((__nv_bfloat162*)oh)[2*i]   = hA;
        ((__nv_bfloat162*)oh)[2*i+1] = hB;
        ((__nv_bfloat162*)ol)[2*i]   = lA;
        ((__nv_bfloat162*)ol)[2*i+1] = lB;
    }
}

// fp32 [R,C] transpose + int8-pair quantize with fixed scale (range/QMAX)
__global__ void transpose_quant(const float* __restrict__ in, int8_t* __restrict__ oh,
                                int8_t* __restrict__ ol, int R, int C,
                                long sIn, long sOut, float invScale)
{
    __shared__ float t[32][33];
    in += (long)blockIdx.z * sIn;
    oh += (long)blockIdx.z * sOut;
    ol += (long)blockIdx.z * sOut;
    const int c0 = blockIdx.x * 32, rr0 = blockIdx.y * 32;
    const int tx = threadIdx.x, ty = threadIdx.y;
    #pragma unroll
    for (int k = 0; k < 32; k += 8)
        t[ty + k][tx] = in[(long)(rr0 + ty + k) * C + c0 + tx];
    __syncthreads();
    #pragma unroll
    for (int k = 0; k < 32; k += 8) {
        float v = t[tx][ty + k] * invScale;
        v = fminf(QMAX, fmaxf(-QMAX, v));
        int8_t hi, lo;
        quant_pair(v, hi, lo);
        long o = (long)(c0 + ty + k) * R + rr0 + tx;
        oh[o] = hi; ol[o] = lo;
    }
}

// s0 = bq . bk
__global__ void s0_kernel(const float* __restrict__ bq, const float* __restrict__ bk,
                          float* __restrict__ s0)
{
    __shared__ float red[256];
    const int tid = threadIdx.x;
    float s = 0.f;
    for (int i = tid; i < DD; i += 256) s += bq[i] * bk[i];
    red[tid] = s; __syncthreads();
    #pragma unroll
    for (int k = 128; k > 0; k >>= 1) {
        if (tid < k) red[tid] += red[tid + k];
        __syncthreads();
    }
    if (tid == 0) s0[0] = red[0];
}

__global__ void gemv_cqck(const float* __restrict__ Wq, const float* __restrict__ Wk,
                          const float* __restrict__ bq, const float* __restrict__ bk,
                          float* __restrict__ cq, float* __restrict__ ck)
{
    const int lane = threadIdx.x & 31, warp = threadIdx.x >> 5;
    const int d = blockIdx.x * 8 + warp;
    float a1 = 0.f, a2 = 0.f;
    for (int i = lane; i < DD; i += 32) {
        a1 += Wq[(long)d * DD + i] * bk[i];
        a2 += Wk[(long)d * DD + i] * bq[i];
    }
    #pragma unroll
    for (int o = 16; o > 0; o >>= 1) {
        a1 += __shfl_xor_sync(0xffffffff, a1, o);
        a2 += __shfl_xor_sync(0xffffffff, a2, o);
    }
    if (lane == 0) { cq[d] = a1; ck[d] = a2; }
}

__global__ void gemv_uw(const float* __restrict__ x, const float* __restrict__ cq,
                        const float* __restrict__ ck, float* __restrict__ u, float* __restrict__ w)
{
    const int lane = threadIdx.x & 31, warp = threadIdx.x >> 5;
    const long r = (long)blockIdx.x * 8 + warp;
    float a1 = 0.f, a2 = 0.f;
    for (int d = lane; d < DD; d += 32) {
        float xv = x[r * DD + d];
        a1 += xv * cq[d];
        a2 += xv * ck[d];
    }
    #pragma unroll
    for (int o = 16; o > 0; o >>= 1) {
        a1 += __shfl_xor_sync(0xffffffff, a1, o);
        a2 += __shfl_xor_sync(0xffffffff, a2, o);
    }
    if (lane == 0) { u[r] = a1; w[r] = a2; }
}

// ---------------------------------------------------------------------------
// Row softmax + entropy; logits = (raw + u_r + w_c + s0)/(8*temp).
// Emits probs as int8 pair (t = e*QMAX, exact rowmax) + per-row scale sp.
// ---------------------------------------------------------------------------
__global__ void softmax_ent(const float* __restrict__ P, const float* __restrict__ u,
                            const float* __restrict__ w, const float* __restrict__ s0,
                            int8_t* __restrict__ P8h, int8_t* __restrict__ P8l,
                            float* __restrict__ sp, float* __restrict__ ent,
                            const float* __restrict__ temp)
{
    __shared__ float red[256];
    const float* p = P + (long)blockIdx.x * SS;
    int8_t* oh = P8h + (long)blockIdx.x * SS;
    int8_t* ol = P8l + (long)blockIdx.x * SS;
    const int tid = threadIdx.x;
    const float scale = 1.0f / (8.0f * temp[0]);
    const float ub = u[blockIdx.x] + s0[0];
    const float* wb = w + (blockIdx.x / SS) * SS;

    float v[8];
    #pragma unroll
    for (int j = 0; j < 8; j++) {
        const int c = tid + j * 256;
        v[j] = (p[c] + ub + wb[c]) * scale;
    }

    float m = v[0];
    #pragma unroll
    for (int j = 1; j < 8; j++) m = fmaxf(m, v[j]);
    red[tid] = m; __syncthreads();
    #pragma unroll
    for (int s = 128; s > 0; s >>= 1) {
        if (tid < s) red[tid] = fmaxf(red[tid], red[tid + s]);
        __syncthreads();
    }
    m = red[0]; __syncthreads();

    float e[8], l = 0.f, t = 0.f;
    #pragma unroll
    for (int j = 0; j < 8; j++) {
        e[j] = __expf(v[j] - m);
        l += e[j];
        t += e[j] * v[j];
    }
    red[tid] = l; __syncthreads();
    #pragma unroll
    for (int s = 128; s > 0; s >>= 1) {
        if (tid < s) red[tid] += red[tid + s];
        __syncthreads();
    }
    l = red[0]; __syncthreads();
    red[tid] = t; __syncthreads();
    #pragma unroll
    for (int s = 128; s > 0; s >>= 1) {
        if (tid < s) red[tid] += red[tid + s];
        __syncthreads();
    }
    t = red[0]; __syncthreads();

    const float inv = 1.0f / l;
    #pragma unroll
    for (int j = 0; j < 8; j++) {
        int8_t hi, lo;
        quant_pair(e[j] * QMAX, hi, lo);        // e in (0,1], exact range use
        oh[tid + j * 256] = hi;
        ol[tid + j * 256] = lo;
    }
    if (tid == 0) {
        sp[blockIdx.x] = inv / QMAX;            // p = sp * (256*hi + lo)
        ent[blockIdx.x] = m + logf(l) - t * inv;
    }
}

// z fp32 -> int8 pair with per-row scale (rowmax/QMAX)
__global__ void zquant(const float* __restrict__ Z, int8_t* __restrict__ oh,
                       int8_t* __restrict__ ol, float* __restrict__ sz)
{
    __shared__ float red[256];
    const float* z = Z + (long)blockIdx.x * DD;
    const int tid = threadIdx.x;
    float4 v = ((const float4*)z)[tid];
    float mx = fmaxf(fmaxf(fabsf(v.x), fabsf(v.y)), fmaxf(fabsf(v.z), fabsf(v.w)));
    red[tid] = mx; __syncthreads();
    #pragma unroll
    for (int k = 128; k > 0; k >>= 1) {
        if (tid < k) red[tid] = fmaxf(red[tid], red[tid + k]);
        __syncthreads();
    }
    const float rmax = fmaxf(red[0], 1e-20f);
    const float inv = QMAX / rmax;
    char4 h4, l4;
    int8_t hi, lo;
    quant_pair(v.x * inv, hi, lo); h4.x = hi; l4.x = lo;
    quant_pair(v.y * inv, hi, lo); h4.y = hi; l4.y = lo;
    quant_pair(v.z * inv, hi, lo); h4.z = hi; l4.z = lo;
    quant_pair(v.w * inv, hi, lo); h4.w = hi; l4.w = lo;
    ((char4*)(oh + (long)blockIdx.x * DD))[tid] = h4;
    ((char4*)(ol + (long)blockIdx.x * DD))[tid] = l4;
    if (tid == 0) sz[blockIdx.x] = rmax / QMAX;
}

__global__ void ent_reduce(const float* __restrict__ ent, float* __restrict__ out)
{
    __shared__ float red[256];
    const int tid = threadIdx.x;
    float s = 0.f;
    for (int i = tid; i < MS; i += 256) s += ent[i];
    red[tid] = s; __syncthreads();
    #pragma unroll
    for (int k = 128; k > 0; k >>= 1) {
        if (tid < k) red[tid] += red[tid + k];
        __syncthreads();
    }
    if (tid == 0) out[0] = red[0] / (float)MS;
}

// ---------------------------------------------------------------------------
extern "C" void kernel_launch(void* const* d_in, const int* in_sizes, int n_in,
                              void* d_out, int out_size)
{
    const float* x    = (const float*)d_in[0];
    const float* Wq   = (const float*)d_in[1];
    const float* bq   = (const float*)d_in[2];
    const float* Wk   = (const float*)d_in[3];
    const float* bk   = (const float*)d_in[4];
    const float* Wv   = (const float*)d_in[5];
    const float* bv   = (const float*)d_in[6];
    const float* temp = (const float*)d_in[7];
    float* out = (float*)d_out;

    __nv_bfloat16 *xh, *xl, *wqh, *wql, *wkh, *wkl, *mth, *mtl, *yh, *yl;
    int8_t *p8h, *p8l, *xt8h, *xt8l, *wvt8h, *wvt8l, *z8h, *z8l;
    float *mtp, *p, *sp, *z, *sz, *cq, *ck, *u, *w, *s0, *ent;
    cudaGetSymbolAddress((void**)&xh,  g_xh);   cudaGetSymbolAddress((void**)&xl,  g_xl);
    cudaGetSymbolAddress((void**)&wqh, g_wqh);  cudaGetSymbolAddress((void**)&wql, g_wql);
    cudaGetSymbolAddress((void**)&wkh, g_wkh);  cudaGetSymbolAddress((void**)&wkl, g_wkl);
    cudaGetSymbolAddress((void**)&mtp, g_mtp);
    cudaGetSymbolAddress((void**)&mth, g_mth);  cudaGetSymbolAddress((void**)&mtl, g_mtl);
    cudaGetSymbolAddress((void**)&yh,  g_yh);   cudaGetSymbolAddress((void**)&yl,  g_yl);
    cudaGetSymbolAddress((void**)&p,   g_p);
    cudaGetSymbolAddress((void**)&p8h, g_p8h);  cudaGetSymbolAddress((void**)&p8l, g_p8l);
    cudaGetSymbolAddress((void**)&sp,  g_sp);
    cudaGetSymbolAddress((void**)&xt8h, g_xt8h); cudaGetSymbolAddress((void**)&xt8l, g_xt8l);
    cudaGetSymbolAddress((void**)&wvt8h, g_wvt8h); cudaGetSymbolAddress((void**)&wvt8l, g_wvt8l);
    cudaGetSymbolAddress((void**)&z,   g_z);
    cudaGetSymbolAddress((void**)&z8h, g_z8h);  cudaGetSymbolAddress((void**)&z8l, g_z8l);
    cudaGetSymbolAddress((void**)&sz,  g_sz);
    cudaGetSymbolAddress((void**)&cq,  g_cq);   cudaGetSymbolAddress((void**)&ck,  g_ck);
    cudaGetSymbolAddress((void**)&u,   g_u);    cudaGetSymbolAddress((void**)&w,   g_w);
    cudaGetSymbolAddress((void**)&s0,  g_s0);   cudaGetSymbolAddress((void**)&ent, g_ent);

    cudaFuncSetAttribute(mma_gemm<0>,    cudaFuncAttributeMaxDynamicSharedMemorySize, SMEMB);
    cudaFuncSetAttribute(mma_gemm<2>,    cudaFuncAttributeMaxDynamicSharedMemorySize, SMEMB);
    cudaFuncSetAttribute(mma_gemm_i8<0>, cudaFuncAttributeMaxDynamicSharedMemorySize, SMEMB);
    cudaFuncSetAttribute(mma_gemm_i8<1>, cudaFuncAttributeMaxDynamicSharedMemorySize, SMEMB);

    dim3 tb(32, 8);
    const float SX = QX_RANGE / QMAX;   // x^T int8 scale
    const float SW = QW_RANGE / QMAX;   // Wv^T int8 scale

    // 1) splits + int8 transposes
    split_x_kernel<<<(MS*DD/4 + 255)/256, 256>>>(x, xh, xl, MS*DD/4);
    split_kernel<<<(DD*DD/4 + 255)/256, 256>>>(Wq, wqh, wql, DD*DD/4);
    split_kernel<<<(DD*DD/4 + 255)/256, 256>>>(Wk, wkh, wkl, DD*DD/4);
    // x^T int8 pair per batch ([S,D] -> [D,S]), fixed 8-sigma scale
    transpose_quant<<<dim3(DD/32, SS/32, BB), tb>>>(x, xt8h, xt8l, SS, DD,
                                                    (long)SS*DD, (long)DD*SS, 1.0f/SX);
    // Wv^T int8 pair ([D,D] -> [D,D])
    transpose_quant<<<dim3(DD/32, DD/32, 1), tb>>>(Wv, wvt8h, wvt8l, DD, DD,
                                                   0, 0, 1.0f/SW);

    // bias rank-1 terms (exact fp32)
    s0_kernel<<<1, 256>>>(bq, bk, s0);
    gemv_cqck<<<DD/8, 256>>>(Wq, Wk, bq, bk, cq, ck);
    gemv_uw<<<MS/8, 256>>>(x, cq, ck, u, w);

    // 2) M^T = Wk Wq^T, K-split over 4 partials, reduce -> bf16 pair
    mma_gemm<0><<<dim3(DD/128, DD/128, 4), 256, SMEMB>>>(
        wkh, wkl, wqh, wql, mtp, nullptr, nullptr,
        DD, 256, DD, DD, 256, 256, (long)DD*DD);
    mt_reduce_split<<<(DD*DD/4 + 255)/256, 256>>>(mtp, mth, mtl, DD*DD/4);

    // 3) y = x M -> bf16 pair
    mma_gemm<2><<<dim3(DD/128, MS/128, 1), 256, SMEMB>>>(
        xh, xl, mth, mtl, nullptr, yh, yl,
        DD, DD, DD, DD, 0, 0, 0);

    // 4) scores = y x^T per batch -> fp32
    mma_gemm<0><<<dim3(SS/128, SS/128, BB), 256, SMEMB>>>(
        yh, yl, xh, xl, p, nullptr, nullptr,
        SS, DD, DD, DD, (long)SS*DD, (long)SS*DD, (long)SS*SS);

    // 5) softmax + entropy -> probs int8 pair + sp
    softmax_ent<<<MS, 256>>>(p, u, w, s0, p8h, p8l, sp, ent, temp);

    // 6) z = p x per batch (IMMA int8) -> fp32
    mma_gemm_i8<0><<<dim3(DD/128, SS/128, BB), 256, SMEMB>>>(
        p8h, p8l, xt8h, xt8l, sp, SS, SX, nullptr, z,
        DD, SS, SS, SS, (long)SS*SS, (long)DD*SS, (long)SS*DD);

    // 7) z -> int8 pair (per-row scale)
    zquant<<<MS, 256>>>(z, z8h, z8l, sz);

    // 8) out = z Wv + bv (IMMA int8) -> fp32
    mma_gemm_i8<1><<<dim3(DD/128, MS/128, 1), 256, SMEMB>>>(
        z8h, z8l, wvt8h, wvt8l, sz, 0, SW, bv, out,
        DD, DD, DD, DD, 0, 0, 0);

    // 9) entropy mean scalar
    ent_reduce<<<1, 256>>>(ent, out + OUT_ELEMS);
}

// round 14
// speedup vs baseline: 2.5512x; 2.5512x over previous
#include <cuda_runtime.h>
#include <cuda_bf16.h>
#include <cuda_fp16.h>
#include <math.h>
#include <stdint.h>

// Problem dims (fixed)
#define BB 4
#define SS 2048
#define DD 1024
#define MS (BB*SS)          // 8192 rows total
#define OUT_ELEMS (MS*DD)

// --- bf16 split GEMM smem geometry: rows hold hi(64B)|lo(64B), stride 144B ---
#define ROWB   144
#define ATILEB (128*ROWB)
#define STAGEB (2*ATILEB)              // A + B tile = 36864 B
#define NSTAGE 3
#define SMEMB  (NSTAGE*STAGEB)         // 110592 B -> 2 CTAs/SM

// --- fp16 single GEMM smem geometry: rows 64B data + 16B pad -> 80B ---
#define ROWB2   80
#define ATIL2   (128*ROWB2)
#define STAGE2  (2*ATIL2)              // 20480 B
#define SMEM2   (NSTAGE*STAGE2)        // 61440 B

// ---------------------------------------------------------------------------
// PTX helpers (sm_80-level only: cp.async, ldmatrix, mma.sync)
// ---------------------------------------------------------------------------
__device__ __forceinline__ uint32_t smem_u32(const void* p) {
    uint32_t a;
    asm("{ .reg .u64 t; cvta.to.shared.u64 t, %1; cvt.u32.u64 %0, t; }" : "=r"(a) : "l"(p));
    return a;
}
#define CP16(d, s) asm volatile("cp.async.cg.shared.global [%0], [%1], 16;" :: "r"(d), "l"(s))
#define CPCOMMIT() asm volatile("cp.async.commit_group;" ::: "memory")
#define CPWAIT(n)  asm volatile("cp.async.wait_group %0;" :: "n"(n) : "memory")

__device__ __forceinline__ void ldsm4(uint32_t* r, uint32_t a) {
    asm volatile("ldmatrix.sync.aligned.m8n8.x4.shared.b16 {%0,%1,%2,%3}, [%4];"
                 : "=r"(r[0]), "=r"(r[1]), "=r"(r[2]), "=r"(r[3]) : "r"(a));
}
__device__ __forceinline__ void mma16816(float* c, const uint32_t* a, const uint32_t* b) {
    asm volatile("mma.sync.aligned.m16n8k16.row.col.f32.bf16.bf16.f32 "
                 "{%0,%1,%2,%3}, {%4,%5,%6,%7}, {%8,%9}, {%0,%1,%2,%3};"
                 : "+f"(c[0]), "+f"(c[1]), "+f"(c[2]), "+f"(c[3])
                 : "r"(a[0]), "r"(a[1]), "r"(a[2]), "r"(a[3]), "r"(b[0]), "r"(b[1]));
}
__device__ __forceinline__ void mma16816h(float* c, const uint32_t* a, const uint32_t* b) {
    asm volatile("mma.sync.aligned.m16n8k16.row.col.f32.f16.f16.f32 "
                 "{%0,%1,%2,%3}, {%4,%5,%6,%7}, {%8,%9}, {%0,%1,%2,%3};"
                 : "+f"(c[0]), "+f"(c[1]), "+f"(c[2]), "+f"(c[3])
                 : "r"(a[0]), "r"(a[1]), "r"(a[2]), "r"(a[3]), "r"(b[0]), "r"(b[1]));
}

// ---------------------------------------------------------------------------
// Static scratch (allocation-free rule)
// ---------------------------------------------------------------------------
__device__ __align__(256) __nv_bfloat16 g_xh[MS*DD], g_xl[MS*DD];
__device__ __align__(256) __half         g_x16[MS*DD];
__device__ __align__(256) __half         g_xt16[MS*DD];                 // per-batch x^T
__device__ __align__(256) __nv_bfloat16 g_wqh[DD*DD], g_wql[DD*DD];
__device__ __align__(256) __nv_bfloat16 g_wkh[DD*DD], g_wkl[DD*DD];
__device__ __align__(256) __half         g_wvt16[DD*DD];                 // Wv^T fp16
__device__ __align__(256) float          g_mtp[4*DD*DD];                 // M^T K-split partials
__device__ __align__(256) __nv_bfloat16 g_mth[DD*DD], g_mtl[DD*DD];     // M^T = Wk Wq^T
__device__ __align__(256) __nv_bfloat16 g_yh[MS*DD], g_yl[MS*DD];       // y = x M
__device__ __align__(256) float          g_p[(size_t)BB*SS*SS];
__device__ __align__(256) __half         g_p16[(size_t)BB*SS*SS];
__device__ __align__(256) __half         g_z16[MS*DD];                   // z = p x
__device__ __align__(256) float          g_cq[DD], g_ck[DD], g_u[MS], g_w[MS], g_s0[1];
__device__ __align__(256) float          g_ent[MS];

// ---------------------------------------------------------------------------
// bf16 split GEMM via mma.sync:
//   C[M,N] = (Ah+Al)[.,K] x (Bh+Bl)[.,K]^T   (3 MMAs: hh + hl + lh)
// CTA tile 128x128, K-chunk 32, 256 threads = 8 warps (4 M x 2 N),
// 3-stage cp.async ring, ONE barrier/chunk, 2 CTAs/SM.
// EPI 0: fp32 store.  EPI 2: bf16 hi/lo split store (Oh/Ol, row stride N).
// ---------------------------------------------------------------------------
template<int EPI>
__global__ __launch_bounds__(256, 2)
void mma_gemm(const __nv_bfloat16* __restrict__ Ah, const __nv_bfloat16* __restrict__ Al,
              const __nv_bfloat16* __restrict__ Bh, const __nv_bfloat16* __restrict__ Bl,
              float* __restrict__ Cf, __nv_bfloat16* __restrict__ Oh, __nv_bfloat16* __restrict__ Ol,
              int N, int K, int lda, int ldb, long sA, long sB, long sC)
{
    extern __shared__ char sm[];
    const uint32_t sb = smem_u32(sm);
    const int tid = threadIdx.x, lane = tid & 31, warp = tid >> 5;
    const int wm = warp & 3, wn = warp >> 2;     // 4 M-warps x 2 N-warps
    const int bz = blockIdx.z;

    const __nv_bfloat16* srcA[2] = {
        Ah + (long)bz * sA + (long)blockIdx.y * 128 * lda,
        Al + (long)bz * sA + (long)blockIdx.y * 128 * lda };
    const __nv_bfloat16* srcB[2] = {
        Bh + (long)bz * sB + (long)blockIdx.x * 128 * ldb,
        Bl + (long)bz * sB + (long)blockIdx.x * 128 * ldb };

    float acc[2][8][4];
    #pragma unroll
    for (int a = 0; a < 2; a++)
        #pragma unroll
        for (int b = 0; b < 8; b++)
            #pragma unroll
            for (int c = 0; c < 4; c++) acc[a][b][c] = 0.f;

    const int NC = K >> 5;

    auto load_stage = [&](int c) {
        const uint32_t dstS = sb + (uint32_t)(c % NSTAGE) * STAGEB;
        const long kof = (long)c * 32;
        #pragma unroll
        for (int p = 0; p < 4; p++) {
            const int u = tid + p * 256;
            const int r = u >> 3, seg = u & 7;
            const int hl = seg >> 2;
            const long so = kof + (seg & 3) * 8;
            CP16(dstS + r * ROWB + seg * 16,          srcA[hl] + (long)r * lda + so);
            CP16(dstS + ATILEB + r * ROWB + seg * 16, srcB[hl] + (long)r * ldb + so);
        }
        CPCOMMIT();
    };

    load_stage(0);
    if (NC > 1) load_stage(1);

    for (int c = 0; c < NC; c++) {
        if (c + 2 <= NC) { CPWAIT(1); } else { CPWAIT(0); }
        __syncthreads();
        if (c + 2 < NC) load_stage(c + 2);

        const uint32_t stb = sb + (uint32_t)(c % NSTAGE) * STAGEB;
        #pragma unroll
        for (int ks = 0; ks < 2; ks++) {
            uint32_t aHi[2][4], aLo[2][4];
            const int rA   = wm * 32 + (lane & 15);
            const int colA = ks * 32 + ((lane >> 4) << 4);
            #pragma unroll
            for (int mf = 0; mf < 2; mf++) {
                const uint32_t ad = stb + (rA + mf * 16) * ROWB + colA;
                ldsm4(aHi[mf], ad);
                ldsm4(aLo[mf], ad + 64);
            }
            const int rB   = wn * 64 + ((lane >> 4) & 1) * 8 + (lane & 7);
            const int colB = ks * 32 + ((lane >> 3) & 1) * 16;
            #pragma unroll
            for (int g = 0; g < 4; g++) {
                uint32_t bh4[4], bl4[4];
                const uint32_t bd = stb + ATILEB + (rB + g * 16) * ROWB + colB;
                ldsm4(bh4, bd);
                ldsm4(bl4, bd + 64);
                #pragma unroll
                for (int mf = 0; mf < 2; mf++) {
                    mma16816(acc[mf][2*g],   aHi[mf], bh4);
                    mma16816(acc[mf][2*g],   aHi[mf], bl4);
                    mma16816(acc[mf][2*g],   aLo[mf], bh4);
                    mma16816(acc[mf][2*g+1], aHi[mf], bh4 + 2);
                    mma16816(acc[mf][2*g+1], aHi[mf], bl4 + 2);
                    mma16816(acc[mf][2*g+1], aLo[mf], bh4 + 2);
                }
            }
        }
    }

    // ---- epilogue ----
    const long rbase = (long)blockIdx.y * 128 + wm * 32 + (lane >> 2);
    const int  gcol0 = blockIdx.x * 128;

    #pragma unroll
    for (int mf = 0; mf < 2; mf++)
        #pragma unroll
        for (int rh = 0; rh < 2; rh++) {
            const long r = rbase + mf * 16 + rh * 8;
            #pragma unroll
            for (int nf = 0; nf < 8; nf++) {
                const int col = gcol0 + wn * 64 + 2 * (lane & 3) + nf * 8;
                float v0 = acc[mf][nf][rh * 2 + 0];
                float v1 = acc[mf][nf][rh * 2 + 1];
                if (EPI == 0) {
                    float2 f2; f2.x = v0; f2.y = v1;
                    *(float2*)(Cf + (long)bz * sC + r * N + col) = f2;
                } else {
                    __nv_bfloat16 h0 = __float2bfloat16(v0);
                    __nv_bfloat16 h1 = __float2bfloat16(v1);
                    __nv_bfloat162 hh; hh.x = h0; hh.y = h1;
                    __nv_bfloat162 ll;
                    ll.x = __float2bfloat16(v0 - __bfloat162float(h0));
                    ll.y = __float2bfloat16(v1 - __bfloat162float(h1));
                    *(__nv_bfloat162*)(Oh + (long)bz * sC + r * N + col) = hh;
                    *(__nv_bfloat162*)(Ol + (long)bz * sC + r * N + col) = ll;
                }
            }
        }
}

// ---------------------------------------------------------------------------
// fp16 single-term GEMM: C[M,N] = A[.,K] x B[.,K]^T, fp32 accum.
// EPI 0: fp32 store + bias.  EPI 1: fp16 store.
// ---------------------------------------------------------------------------
template<int EPI>
__global__ __launch_bounds__(256, 2)
void mma_gemm_h1(const __half* __restrict__ A, const __half* __restrict__ B,
                 float* __restrict__ Cf, __half* __restrict__ Oz,
                 const float* __restrict__ bias,
                 int N, int K, int lda, int ldb, long sA, long sB, long sC)
{
    extern __shared__ char sm[];
    const uint32_t sb = smem_u32(sm);
    const int tid = threadIdx.x, lane = tid & 31, warp = tid >> 5;
    const int wm = warp & 3, wn = warp >> 2;
    const int bz = blockIdx.z;

    const __half* srcA = A + (long)bz * sA + (long)blockIdx.y * 128 * lda;
    const __half* srcB = B + (long)bz * sB + (long)blockIdx.x * 128 * ldb;

    float acc[2][8][4];
    #pragma unroll
    for (int a = 0; a < 2; a++)
        #pragma unroll
        for (int b = 0; b < 8; b++)
            #pragma unroll
            for (int c = 0; c < 4; c++) acc[a][b][c] = 0.f;

    const int NC = K >> 5;

    auto load_stage = [&](int c) {
        const uint32_t dstS = sb + (uint32_t)(c % NSTAGE) * STAGE2;
        const long kof = (long)c * 32;
        #pragma unroll
        for (int p = 0; p < 2; p++) {
            const int u = tid + p * 256;
            const int r = u >> 2, s = u & 3;
            const long so = kof + s * 8;
            CP16(dstS + r * ROWB2 + s * 16,         srcA + (long)r * lda + so);
            CP16(dstS + ATIL2 + r * ROWB2 + s * 16, srcB + (long)r * ldb + so);
        }
        CPCOMMIT();
    };

    load_stage(0);
    if (NC > 1) load_stage(1);

    for (int c = 0; c < NC; c++) {
        if (c + 2 <= NC) { CPWAIT(1); } else { CPWAIT(0); }
        __syncthreads();
        if (c + 2 < NC) load_stage(c + 2);

        const uint32_t stb = sb + (uint32_t)(c % NSTAGE) * STAGE2;
        #pragma unroll
        for (int ks = 0; ks < 2; ks++) {
            uint32_t aF[2][4];
            const int rA   = wm * 32 + (lane & 15);
            const int colA = ks * 32 + ((lane >> 4) << 4);
            #pragma unroll
            for (int mf = 0; mf < 2; mf++)
                ldsm4(aF[mf], stb + (rA + mf * 16) * ROWB2 + colA);
            const int rB   = wn * 64 + ((lane >> 4) & 1) * 8 + (lane & 7);
            const int colB = ks * 32 + ((lane >> 3) & 1) * 16;
            #pragma unroll
            for (int g = 0; g < 4; g++) {
                uint32_t b4[4];
                ldsm4(b4, stb + ATIL2 + (rB + g * 16) * ROWB2 + colB);
                #pragma unroll
                for (int mf = 0; mf < 2; mf++) {
                    mma16816h(acc[mf][2*g],   aF[mf], b4);
                    mma16816h(acc[mf][2*g+1], aF[mf], b4 + 2);
                }
            }
        }
    }

    const long rbase = (long)blockIdx.y * 128 + wm * 32 + (lane >> 2);
    const int  gcol0 = blockIdx.x * 128;
    #pragma unroll
    for (int mf = 0; mf < 2; mf++)
        #pragma unroll
        for (int rh = 0; rh < 2; rh++) {
            const long r = rbase + mf * 16 + rh * 8;
            #pragma unroll
            for (int nf = 0; nf < 8; nf++) {
                const int col = gcol0 + wn * 64 + 2 * (lane & 3) + nf * 8;
                float v0 = acc[mf][nf][rh * 2 + 0];
                float v1 = acc[mf][nf][rh * 2 + 1];
                if (EPI == 0) {
                    if (bias) { v0 += bias[col]; v1 += bias[col + 1]; }
                    float2 f2; f2.x = v0; f2.y = v1;
                    *(float2*)(Cf + (long)bz * sC + r * N + col) = f2;
                } else {
                    __half2 hv; hv.x = __float2half(v0); hv.y = __float2half(v1);
                    *(__half2*)(Oz + (long)bz * sC + r * N + col) = hv;
                }
            }
        }
}

// ---------------------------------------------------------------------------
// x -> bf16 hi/lo + fp16 (float4 vectorized)
// ---------------------------------------------------------------------------
__global__ void split_x_kernel(const float* __restrict__ in, __nv_bfloat16* __restrict__ oh,
                               __nv_bfloat16* __restrict__ ol, __half* __restrict__ o16, int n4)
{
    int i = blockIdx.x * 256 + threadIdx.x;
    if (i < n4) {
        float4 v = ((const float4*)in)[i];
        __nv_bfloat16 h0 = __float2bfloat16(v.x), h1 = __float2bfloat16(v.y);
        __nv_bfloat16 h2 = __float2bfloat16(v.z), h3 = __float2bfloat16(v.w);
        __nv_bfloat162 hA; hA.x = h0; hA.y = h1;
        __nv_bfloat162 hB; hB.x = h2; hB.y = h3;
        __nv_bfloat162 lA, lB;
        lA.x = __float2bfloat16(v.x - __bfloat162float(h0));
        lA.y = __float2bfloat16(v.y - __bfloat162float(h1));
        lB.x = __float2bfloat16(v.z - __bfloat162float(h2));
        lB.y = __float2bfloat16(v.w - __bfloat162float(h3));
        ((__nv_bfloat162*)oh)[2*i]   = hA;
        ((__nv_bfloat162*)oh)[2*i+1] = hB;
        ((__nv_bfloat162*)ol)[2*i]   = lA;
        ((__nv_bfloat162*)ol)[2*i+1] = lB;
        __half2 a; a.x = __float2half(v.x); a.y = __float2half(v.y);
        __half2 b; b.x = __float2half(v.z); b.y = __float2half(v.w);
        ((__half2*)o16)[2*i]   = a;
        ((__half2*)o16)[2*i+1] = b;
    }
}

// plain elementwise fp32 -> bf16 hi/lo
__global__ void split_kernel(const float* __restrict__ in, __nv_bfloat16* __restrict__ oh,
                             __nv_bfloat16* __restrict__ ol, int n4)
{
    int i = blockIdx.x * 256 + threadIdx.x;
    if (i < n4) {
        float4 v = ((const float4*)in)[i];
        __nv_bfloat16 h0 = __float2bfloat16(v.x), h1 = __float2bfloat16(v.y);
        __nv_bfloat16 h2 = __float2bfloat16(v.z), h3 = __float2bfloat16(v.w);
        __nv_bfloat162 hA; hA.x = h0; hA.y = h1;
        __nv_bfloat162 hB; hB.x = h2; hB.y = h3;
        __nv_bfloat162 lA, lB;
        lA.x = __float2bfloat16(v.x - __bfloat162float(h0));
        lA.y = __float2bfloat16(v.y - __bfloat162float(h1));
        lB.x = __float2bfloat16(v.z - __bfloat162float(h2));
        lB.y = __float2bfloat16(v.w - __bfloat162float(h3));
        ((__nv_bfloat162*)oh)[2*i]   = hA;
        ((__nv_bfloat162*)oh)[2*i+1] = hB;
        ((__nv_bfloat162*)ol)[2*i]   = lA;
        ((__nv_bfloat162*)ol)[2*i+1] = lB;
    }
}

// MT partials (4) -> sum -> bf16 hi/lo
__global__ void mt_reduce_split(const float* __restrict__ parts, __nv_bfloat16* __restrict__ oh,
                                __nv_bfloat16* __restrict__ ol, int n4)
{
    int i = blockIdx.x * 256 + threadIdx.x;
    if (i < n4) {
        float4 s = ((const float4*)parts)[i];
        #pragma unroll
        for (int p = 1; p < 4; p++) {
            float4 t = ((const float4*)(parts + (size_t)p * DD * DD))[i];
            s.x += t.x; s.y += t.y; s.z += t.z; s.w += t.w;
        }
        __nv_bfloat16 h0 = __float2bfloat16(s.x), h1 = __float2bfloat16(s.y);
        __nv_bfloat16 h2 = __float2bfloat16(s.z), h3 = __float2bfloat16(s.w);
        __nv_bfloat162 hA; hA.x = h0; hA.y = h1;
        __nv_bfloat162 hB; hB.x = h2; hB.y = h3;
        __nv_bfloat162 lA, lB;
        lA.x = __float2bfloat16(s.x - __bfloat162float(h0));
        lA.y = __float2bfloat16(s.y - __bfloat162float(h1));
        lB.x = __float2bfloat16(s.z - __bfloat162float(h2));
        lB.y = __float2bfloat16(s.w - __bfloat162float(h3));
        ((__nv_bfloat162*)oh)[2*i]   = hA;
        ((__nv_bfloat162*)oh)[2*i+1] = hB;
        ((__nv_bfloat162*)ol)[2*i]   = lA;
        ((__nv_bfloat162*)ol)[2*i+1] = lB;
    }
}

// fp32 [R,C] -> fp16 [C,R] transpose (Wv -> Wv^T)
__global__ void transpose_f2h(const float* __restrict__ in, __half* __restrict__ out,
                              int R, int C)
{
    __shared__ float t[32][33];
    const int c0 = blockIdx.x * 32, rr0 = blockIdx.y * 32;
    const int tx = threadIdx.x, ty = threadIdx.y;
    #pragma unroll
    for (int k = 0; k < 32; k += 8)
        t[ty + k][tx] = in[(long)(rr0 + ty + k) * C + c0 + tx];
    __syncthreads();
    #pragma unroll
    for (int k = 0; k < 32; k += 8)
        out[(long)(c0 + ty + k) * R + rr0 + tx] = __float2half(t[tx][ty + k]);
}

// Batched fp16 transpose: [R,C] -> [C,R]  (x16 -> x^T per batch)
__global__ void transpose_h(const __half* __restrict__ in, __half* __restrict__ out,
                            int R, int C, long sIn, long sOut)
{
    __shared__ __half t[32][34];
    in  += (long)blockIdx.z * sIn;
    out += (long)blockIdx.z * sOut;
    const int c0 = blockIdx.x * 32, rr0 = blockIdx.y * 32;
    const int tx = threadIdx.x, ty = threadIdx.y;
    #pragma unroll
    for (int k = 0; k < 32; k += 8)
        t[ty + k][tx] = in[(long)(rr0 + ty + k) * C + c0 + tx];
    __syncthreads();
    #pragma unroll
    for (int k = 0; k < 32; k += 8)
        out[(long)(c0 + ty + k) * R + rr0 + tx] = t[tx][ty + k];
}

// s0 = bq . bk
__global__ void s0_kernel(const float* __restrict__ bq, const float* __restrict__ bk,
                          float* __restrict__ s0)
{
    __shared__ float red[256];
    const int tid = threadIdx.x;
    float s = 0.f;
    for (int i = tid; i < DD; i += 256) s += bq[i] * bk[i];
    red[tid] = s; __syncthreads();
    #pragma unroll
    for (int k = 128; k > 0; k >>= 1) {
        if (tid < k) red[tid] += red[tid + k];
        __syncthreads();
    }
    if (tid == 0) s0[0] = red[0];
}

// cq = Wq bk, ck = Wk bq (warp per output element)
__global__ void gemv_cqck(const float* __restrict__ Wq, const float* __restrict__ Wk,
                          const float* __restrict__ bq, const float* __restrict__ bk,
                          float* __restrict__ cq, float* __restrict__ ck)
{
    const int lane = threadIdx.x & 31, warp = threadIdx.x >> 5;
    const int d = blockIdx.x * 8 + warp;
    float a1 = 0.f, a2 = 0.f;
    for (int i = lane; i < DD; i += 32) {
        a1 += Wq[(long)d * DD + i] * bk[i];
        a2 += Wk[(long)d * DD + i] * bq[i];
    }
    #pragma unroll
    for (int o = 16; o > 0; o >>= 1) {
        a1 += __shfl_xor_sync(0xffffffff, a1, o);
        a2 += __shfl_xor_sync(0xffffffff, a2, o);
    }
    if (lane == 0) { cq[d] = a1; ck[d] = a2; }
}

// u = x cq, w = x ck (warp per row)
__global__ void gemv_uw(const float* __restrict__ x, const float* __restrict__ cq,
                        const float* __restrict__ ck, float* __restrict__ u, float* __restrict__ w)
{
    const int lane = threadIdx.x & 31, warp = threadIdx.x >> 5;
    const long r = (long)blockIdx.x * 8 + warp;
    float a1 = 0.f, a2 = 0.f;
    for (int d = lane; d < DD; d += 32) {
        float xv = x[r * DD + d];
        a1 += xv * cq[d];
        a2 += xv * ck[d];
    }
    #pragma unroll
    for (int o = 16; o > 0; o >>= 1) {
        a1 += __shfl_xor_sync(0xffffffff, a1, o);
        a2 += __shfl_xor_sync(0xffffffff, a2, o);
    }
    if (lane == 0) { u[r] = a1; w[r] = a2; }
}

// ---------------------------------------------------------------------------
// Row softmax + entropy; logits = (raw + u_r + w_c + s0)/(8*temp); probs fp16.
// Warp-shuffle reductions, fused (l,t) cross-warp stage: 4 barriers/block.
// ---------------------------------------------------------------------------
__global__ void softmax_ent(const float* __restrict__ P, const float* __restrict__ u,
                            const float* __restrict__ w, const float* __restrict__ s0,
                            __half* __restrict__ P16, float* __restrict__ ent,
                            const float* __restrict__ temp)
{
    __shared__ float sred[20];
    const float* p = P + (long)blockIdx.x * SS;
    __half* o = P16 + (long)blockIdx.x * SS;
    const int tid = threadIdx.x, lane = tid & 31, wid = tid >> 5;
    const float scale = 1.0f / (8.0f * temp[0]);
    const float ub = u[blockIdx.x] + s0[0];
    const float* wb = w + (blockIdx.x / SS) * SS;

    float v[8];
    #pragma unroll
    for (int j = 0; j < 8; j++) {
        const int c = tid + j * 256;
        v[j] = (p[c] + ub + wb[c]) * scale;
    }

    float m = v[0];
    #pragma unroll
    for (int j = 1; j < 8; j++) m = fmaxf(m, v[j]);
    #pragma unroll
    for (int s = 16; s > 0; s >>= 1) m = fmaxf(m, __shfl_xor_sync(0xffffffff, m, s));
    if (lane == 0) sred[wid] = m;
    __syncthreads();
    if (wid == 0) {
        float t2 = (lane < 8) ? sred[lane] : -3.4e38f;
        #pragma unroll
        for (int s = 4; s > 0; s >>= 1) t2 = fmaxf(t2, __shfl_xor_sync(0xffffffff, t2, s));
        if (lane == 0) sred[16] = t2;
    }
    __syncthreads();
    m = sred[16];

    float e[8], l = 0.f, t = 0.f;
    #pragma unroll
    for (int j = 0; j < 8; j++) {
        e[j] = __expf(v[j] - m);
        l += e[j];
        t += e[j] * v[j];
    }
    #pragma unroll
    for (int s = 16; s > 0; s >>= 1) {
        l += __shfl_xor_sync(0xffffffff, l, s);
        t += __shfl_xor_sync(0xffffffff, t, s);
    }
    if (lane == 0) { sred[wid] = l; sred[8 + wid] = t; }
    __syncthreads();
    if (wid == 0) {
        float a = (lane < 8) ? sred[lane] : 0.f;
        float b = (lane < 8) ? sred[8 + lane] : 0.f;
        #pragma unroll
        for (int s = 4; s > 0; s >>= 1) {
            a += __shfl_xor_sync(0xffffffff, a, s);
            b += __shfl_xor_sync(0xffffffff, b, s);
        }
        if (lane == 0) { sred[17] = a; sred[18] = b; }
    }
    __syncthreads();
    l = sred[17]; t = sred[18];

    const float inv = 1.0f / l;
    #pragma unroll
    for (int j = 0; j < 8; j++)
        o[tid + j * 256] = __float2half(e[j] * inv);

    if (tid == 0) ent[blockIdx.x] = m + logf(l) - t * inv;
}

__global__ void ent_reduce(const float* __restrict__ ent, float* __restrict__ out)
{
    __shared__ float red[256];
    const int tid = threadIdx.x;
    float s = 0.f;
    for (int i = tid; i < MS; i += 256) s += ent[i];
    red[tid] = s; __syncthreads();
    #pragma unroll
    for (int k = 128; k > 0; k >>= 1) {
        if (tid < k) red[tid] += red[tid + k];
        __syncthreads();
    }
    if (tid == 0) out[0] = red[0] / (float)MS;
}

// ---------------------------------------------------------------------------
extern "C" void kernel_launch(void* const* d_in, const int* in_sizes, int n_in,
                              void* d_out, int out_size)
{
    const float* x    = (const float*)d_in[0];
    const float* Wq   = (const float*)d_in[1];
    const float* bq   = (const float*)d_in[2];
    const float* Wk   = (const float*)d_in[3];
    const float* bk   = (const float*)d_in[4];
    const float* Wv   = (const float*)d_in[5];
    const float* bv   = (const float*)d_in[6];
    const float* temp = (const float*)d_in[7];
    float* out = (float*)d_out;

    __nv_bfloat16 *xh, *xl, *wqh, *wql, *wkh, *wkl, *mth, *mtl, *yh, *yl;
    __half *x16, *xt16, *wvt16, *p16, *z16;
    float *mtp, *p, *cq, *ck, *u, *w, *s0, *ent;
    cudaGetSymbolAddress((void**)&xh,  g_xh);   cudaGetSymbolAddress((void**)&xl,  g_xl);
    cudaGetSymbolAddress((void**)&x16, g_x16);  cudaGetSymbolAddress((void**)&xt16, g_xt16);
    cudaGetSymbolAddress((void**)&wqh, g_wqh);  cudaGetSymbolAddress((void**)&wql, g_wql);
    cudaGetSymbolAddress((void**)&wkh, g_wkh);  cudaGetSymbolAddress((void**)&wkl, g_wkl);
    cudaGetSymbolAddress((void**)&wvt16, g_wvt16);
    cudaGetSymbolAddress((void**)&mtp, g_mtp);
    cudaGetSymbolAddress((void**)&mth, g_mth);  cudaGetSymbolAddress((void**)&mtl, g_mtl);
    cudaGetSymbolAddress((void**)&yh,  g_yh);   cudaGetSymbolAddress((void**)&yl,  g_yl);
    cudaGetSymbolAddress((void**)&p,   g_p);    cudaGetSymbolAddress((void**)&p16, g_p16);
    cudaGetSymbolAddress((void**)&z16, g_z16);
    cudaGetSymbolAddress((void**)&cq,  g_cq);   cudaGetSymbolAddress((void**)&ck,  g_ck);
    cudaGetSymbolAddress((void**)&u,   g_u);    cudaGetSymbolAddress((void**)&w,   g_w);
    cudaGetSymbolAddress((void**)&s0,  g_s0);   cudaGetSymbolAddress((void**)&ent, g_ent);

    cudaFuncSetAttribute(mma_gemm<0>,    cudaFuncAttributeMaxDynamicSharedMemorySize, SMEMB);
    cudaFuncSetAttribute(mma_gemm<2>,    cudaFuncAttributeMaxDynamicSharedMemorySize, SMEMB);
    cudaFuncSetAttribute(mma_gemm_h1<0>, cudaFuncAttributeMaxDynamicSharedMemorySize, SMEM2);
    cudaFuncSetAttribute(mma_gemm_h1<1>, cudaFuncAttributeMaxDynamicSharedMemorySize, SMEM2);

    dim3 tb(32, 8);

    // 1) splits: x -> (bf16 hi/lo, fp16); Wq,Wk -> bf16 hi/lo; Wv -> fp16 transposed
    split_x_kernel<<<(MS*DD/4 + 255)/256, 256>>>(x, xh, xl, x16, MS*DD/4);
    split_kernel<<<(DD*DD/4 + 255)/256, 256>>>(Wq, wqh, wql, DD*DD/4);
    split_kernel<<<(DD*DD/4 + 255)/256, 256>>>(Wk, wkh, wkl, DD*DD/4);
    transpose_f2h<<<dim3(DD/32, DD/32, 1), tb>>>(Wv, wvt16, DD, DD);

    // bias rank-1 terms (exact fp32; zeros in this dataset but handled generally)
    s0_kernel<<<1, 256>>>(bq, bk, s0);
    gemv_cqck<<<DD/8, 256>>>(Wq, Wk, bq, bk, cq, ck);
    gemv_uw<<<MS/8, 256>>>(x, cq, ck, u, w);

    // x^T fp16 per batch (for z GEMM B operand)
    transpose_h<<<dim3(DD/32, SS/32, BB), tb>>>(x16, xt16, SS, DD, (long)SS*DD, (long)DD*SS);

    // 2) M^T = Wk Wq^T, K-split over 4 partials, then reduce+split to bf16
    mma_gemm<0><<<dim3(DD/128, DD/128, 4), 256, SMEMB>>>(
        wkh, wkl, wqh, wql, mtp, nullptr, nullptr,
        DD, 256, DD, DD, 256, 256, (long)DD*DD);
    mt_reduce_split<<<(DD*DD/4 + 255)/256, 256>>>(mtp, mth, mtl, DD*DD/4);

    // 3) y = x M  (NT vs M^T) -> bf16 hi/lo
    mma_gemm<2><<<dim3(DD/128, MS/128, 1), 256, SMEMB>>>(
        xh, xl, mth, mtl, nullptr, yh, yl,
        DD, DD, DD, DD, 0, 0, 0);

    // 4) scores = y x^T per batch -> fp32
    mma_gemm<0><<<dim3(SS/128, SS/128, BB), 256, SMEMB>>>(
        yh, yl, xh, xl, p, nullptr, nullptr,
        SS, DD, DD, DD, (long)SS*DD, (long)SS*DD, (long)SS*SS);

    // 5) softmax + entropy (adds bias rank-1 terms) -> p16
    softmax_ent<<<MS, 256>>>(p, u, w, s0, p16, ent, temp);

    // 6) z = p x per batch (fp16) -> fp16
    mma_gemm_h1<1><<<dim3(DD/128, SS/128, BB), 256, SMEM2>>>(
        p16, xt16, nullptr, z16, nullptr,
        DD, SS, SS, SS, (long)SS*SS, (long)DD*SS, (long)SS*DD);

    // 7) out = z Wv + bv (fp16 MMA, fp32 out)
    mma_gemm_h1<0><<<dim3(DD/128, MS/128, 1), 256, SMEM2>>>(
        z16, wvt16, out, nullptr, bv,
        DD, DD, DD, DD, 0, 0, 0);

    // 8) entropy mean scalar
    ent_reduce<<<1, 256>>>(ent, out + OUT_ELEMS);
}

// round 15
// speedup vs baseline: 2.6006x; 1.0193x over previous
#include <cuda_runtime.h>
#include <cuda_bf16.h>
#include <cuda_fp16.h>
#include <math.h>
#include <stdint.h>

// Problem dims (fixed)
#define BB 4
#define SS 2048
#define DD 1024
#define MS (BB*SS)          // 8192 rows total
#define OUT_ELEMS (MS*DD)

// --- bf16 split GEMM smem geometry: rows hold hi(64B)|lo(64B), stride 144B ---
#define ROWB   144
#define ATILEB (128*ROWB)
#define STAGEB (2*ATILEB)              // A + B tile = 36864 B
#define NSTAGE 3
#define SMEMB  (NSTAGE*STAGEB)         // 110592 B -> 2 CTAs/SM

// --- fp16 single GEMM smem geometry: rows 64B data + 16B pad -> 80B ---
#define ROWB2   80
#define ATIL2   (128*ROWB2)
#define STAGE2  (2*ATIL2)              // 20480 B
#define SMEM2   (NSTAGE*STAGE2)        // 61440 B

// ---------------------------------------------------------------------------
// PTX helpers (sm_80-level only: cp.async, ldmatrix, mma.sync)
// ---------------------------------------------------------------------------
__device__ __forceinline__ uint32_t smem_u32(const void* p) {
    uint32_t a;
    asm("{ .reg .u64 t; cvta.to.shared.u64 t, %1; cvt.u32.u64 %0, t; }" : "=r"(a) : "l"(p));
    return a;
}
#define CP16(d, s) asm volatile("cp.async.cg.shared.global [%0], [%1], 16;" :: "r"(d), "l"(s))
#define CPCOMMIT() asm volatile("cp.async.commit_group;" ::: "memory")
#define CPWAIT(n)  asm volatile("cp.async.wait_group %0;" :: "n"(n) : "memory")

__device__ __forceinline__ void ldsm4(uint32_t* r, uint32_t a) {
    asm volatile("ldmatrix.sync.aligned.m8n8.x4.shared.b16 {%0,%1,%2,%3}, [%4];"
                 : "=r"(r[0]), "=r"(r[1]), "=r"(r[2]), "=r"(r[3]) : "r"(a));
}
__device__ __forceinline__ void mma16816(float* c, const uint32_t* a, const uint32_t* b) {
    asm volatile("mma.sync.aligned.m16n8k16.row.col.f32.bf16.bf16.f32 "
                 "{%0,%1,%2,%3}, {%4,%5,%6,%7}, {%8,%9}, {%0,%1,%2,%3};"
                 : "+f"(c[0]), "+f"(c[1]), "+f"(c[2]), "+f"(c[3])
                 : "r"(a[0]), "r"(a[1]), "r"(a[2]), "r"(a[3]), "r"(b[0]), "r"(b[1]));
}
__device__ __forceinline__ void mma16816h(float* c, const uint32_t* a, const uint32_t* b) {
    asm volatile("mma.sync.aligned.m16n8k16.row.col.f32.f16.f16.f32 "
                 "{%0,%1,%2,%3}, {%4,%5,%6,%7}, {%8,%9}, {%0,%1,%2,%3};"
                 : "+f"(c[0]), "+f"(c[1]), "+f"(c[2]), "+f"(c[3])
                 : "r"(a[0]), "r"(a[1]), "r"(a[2]), "r"(a[3]), "r"(b[0]), "r"(b[1]));
}

// ---------------------------------------------------------------------------
// Static scratch (allocation-free rule)
// ---------------------------------------------------------------------------
__device__ __align__(256) __nv_bfloat16 g_xh[MS*DD], g_xl[MS*DD];
__device__ __align__(256) __half         g_xt16[MS*DD];                 // per-batch x^T fp16
__device__ __align__(256) __nv_bfloat16 g_wqh[DD*DD], g_wql[DD*DD];
__device__ __align__(256) __nv_bfloat16 g_wkh[DD*DD], g_wkl[DD*DD];
__device__ __align__(256) __half         g_wvt16[DD*DD];                 // Wv^T fp16
__device__ __align__(256) float          g_mtp[4*DD*DD];                 // M^T K-split partials
__device__ __align__(256) __nv_bfloat16 g_mth[DD*DD], g_mtl[DD*DD];     // M^T = Wk Wq^T
__device__ __align__(256) __nv_bfloat16 g_yh[MS*DD], g_yl[MS*DD];       // y = x M
__device__ __align__(256) float          g_p[(size_t)BB*SS*SS];
__device__ __align__(256) __half         g_p16[(size_t)BB*SS*SS];
__device__ __align__(256) __half         g_z16[MS*DD];                   // z = p x
__device__ __align__(256) float          g_cq[DD], g_ck[DD], g_u[MS], g_w[MS], g_s0[1];
__device__ __align__(256) float          g_ent[MS];

// ---------------------------------------------------------------------------
// bf16 split GEMM via mma.sync:
//   C[M,N] = (Ah+Al)[.,K] x (Bh+Bl)[.,K]^T   (3 MMAs: hh + hl + lh)
// CTA tile 128x128, K-chunk 32, 256 threads = 8 warps (4 M x 2 N),
// 3-stage cp.async ring, ONE barrier/chunk, 2 CTAs/SM.
// EPI 0: fp32 store.  EPI 2: bf16 hi/lo split store (Oh/Ol, row stride N).
// ---------------------------------------------------------------------------
template<int EPI>
__global__ __launch_bounds__(256, 2)
void mma_gemm(const __nv_bfloat16* __restrict__ Ah, const __nv_bfloat16* __restrict__ Al,
              const __nv_bfloat16* __restrict__ Bh, const __nv_bfloat16* __restrict__ Bl,
              float* __restrict__ Cf, __nv_bfloat16* __restrict__ Oh, __nv_bfloat16* __restrict__ Ol,
              int N, int K, int lda, int ldb, long sA, long sB, long sC)
{
    extern __shared__ char sm[];
    const uint32_t sb = smem_u32(sm);
    const int tid = threadIdx.x, lane = tid & 31, warp = tid >> 5;
    const int wm = warp & 3, wn = warp >> 2;     // 4 M-warps x 2 N-warps
    const int bz = blockIdx.z;

    const __nv_bfloat16* srcA[2] = {
        Ah + (long)bz * sA + (long)blockIdx.y * 128 * lda,
        Al + (long)bz * sA + (long)blockIdx.y * 128 * lda };
    const __nv_bfloat16* srcB[2] = {
        Bh + (long)bz * sB + (long)blockIdx.x * 128 * ldb,
        Bl + (long)bz * sB + (long)blockIdx.x * 128 * ldb };

    float acc[2][8][4];
    #pragma unroll
    for (int a = 0; a < 2; a++)
        #pragma unroll
        for (int b = 0; b < 8; b++)
            #pragma unroll
            for (int c = 0; c < 4; c++) acc[a][b][c] = 0.f;

    const int NC = K >> 5;

    auto load_stage = [&](int c) {
        const uint32_t dstS = sb + (uint32_t)(c % NSTAGE) * STAGEB;
        const long kof = (long)c * 32;
        #pragma unroll
        for (int p = 0; p < 4; p++) {
            const int u = tid + p * 256;
            const int r = u >> 3, seg = u & 7;
            const int hl = seg >> 2;
            const long so = kof + (seg & 3) * 8;
            CP16(dstS + r * ROWB + seg * 16,          srcA[hl] + (long)r * lda + so);
            CP16(dstS + ATILEB + r * ROWB + seg * 16, srcB[hl] + (long)r * ldb + so);
        }
        CPCOMMIT();
    };

    load_stage(0);
    if (NC > 1) load_stage(1);

    for (int c = 0; c < NC; c++) {
        if (c + 2 <= NC) { CPWAIT(1); } else { CPWAIT(0); }
        __syncthreads();
        if (c + 2 < NC) load_stage(c + 2);

        const uint32_t stb = sb + (uint32_t)(c % NSTAGE) * STAGEB;
        #pragma unroll
        for (int ks = 0; ks < 2; ks++) {
            uint32_t aHi[2][4], aLo[2][4];
            const int rA   = wm * 32 + (lane & 15);
            const int colA = ks * 32 + ((lane >> 4) << 4);
            #pragma unroll
            for (int mf = 0; mf < 2; mf++) {
                const uint32_t ad = stb + (rA + mf * 16) * ROWB + colA;
                ldsm4(aHi[mf], ad);
                ldsm4(aLo[mf], ad + 64);
            }
            const int rB   = wn * 64 + ((lane >> 4) & 1) * 8 + (lane & 7);
            const int colB = ks * 32 + ((lane >> 3) & 1) * 16;
            #pragma unroll
            for (int g = 0; g < 4; g++) {
                uint32_t bh4[4], bl4[4];
                const uint32_t bd = stb + ATILEB + (rB + g * 16) * ROWB + colB;
                ldsm4(bh4, bd);
                ldsm4(bl4, bd + 64);
                #pragma unroll
                for (int mf = 0; mf < 2; mf++) {
                    mma16816(acc[mf][2*g],   aHi[mf], bh4);
                    mma16816(acc[mf][2*g],   aHi[mf], bl4);
                    mma16816(acc[mf][2*g],   aLo[mf], bh4);
                    mma16816(acc[mf][2*g+1], aHi[mf], bh4 + 2);
                    mma16816(acc[mf][2*g+1], aHi[mf], bl4 + 2);
                    mma16816(acc[mf][2*g+1], aLo[mf], bh4 + 2);
                }
            }
        }
    }

    // ---- epilogue ----
    const long rbase = (long)blockIdx.y * 128 + wm * 32 + (lane >> 2);
    const int  gcol0 = blockIdx.x * 128;

    #pragma unroll
    for (int mf = 0; mf < 2; mf++)
        #pragma unroll
        for (int rh = 0; rh < 2; rh++) {
            const long r = rbase + mf * 16 + rh * 8;
            #pragma unroll
            for (int nf = 0; nf < 8; nf++) {
                const int col = gcol0 + wn * 64 + 2 * (lane & 3) + nf * 8;
                float v0 = acc[mf][nf][rh * 2 + 0];
                float v1 = acc[mf][nf][rh * 2 + 1];
                if (EPI == 0) {
                    float2 f2; f2.x = v0; f2.y = v1;
                    *(float2*)(Cf + (long)bz * sC + r * N + col) = f2;
                } else {
                    __nv_bfloat16 h0 = __float2bfloat16(v0);
                    __nv_bfloat16 h1 = __float2bfloat16(v1);
                    __nv_bfloat162 hh; hh.x = h0; hh.y = h1;
                    __nv_bfloat162 ll;
                    ll.x = __float2bfloat16(v0 - __bfloat162float(h0));
                    ll.y = __float2bfloat16(v1 - __bfloat162float(h1));
                    *(__nv_bfloat162*)(Oh + (long)bz * sC + r * N + col) = hh;
                    *(__nv_bfloat162*)(Ol + (long)bz * sC + r * N + col) = ll;
                }
            }
        }
}

// ---------------------------------------------------------------------------
// fp16 single-term GEMM: C[M,N] = A[.,K] x B[.,K]^T, fp32 accum.
// EPI 0: fp32 store + bias.  EPI 1: fp16 store.
// ---------------------------------------------------------------------------
template<int EPI>
__global__ __launch_bounds__(256, 2)
void mma_gemm_h1(const __half* __restrict__ A, const __half* __restrict__ B,
                 float* __restrict__ Cf, __half* __restrict__ Oz,
                 const float* __restrict__ bias,
                 int N, int K, int lda, int ldb, long sA, long sB, long sC)
{
    extern __shared__ char sm[];
    const uint32_t sb = smem_u32(sm);
    const int tid = threadIdx.x, lane = tid & 31, warp = tid >> 5;
    const int wm = warp & 3, wn = warp >> 2;
    const int bz = blockIdx.z;

    const __half* srcA = A + (long)bz * sA + (long)blockIdx.y * 128 * lda;
    const __half* srcB = B + (long)bz * sB + (long)blockIdx.x * 128 * ldb;

    float acc[2][8][4];
    #pragma unroll
    for (int a = 0; a < 2; a++)
        #pragma unroll
        for (int b = 0; b < 8; b++)
            #pragma unroll
            for (int c = 0; c < 4; c++) acc[a][b][c] = 0.f;

    const int NC = K >> 5;

    auto load_stage = [&](int c) {
        const uint32_t dstS = sb + (uint32_t)(c % NSTAGE) * STAGE2;
        const long kof = (long)c * 32;
        #pragma unroll
        for (int p = 0; p < 2; p++) {
            const int u = tid + p * 256;
            const int r = u >> 2, s = u & 3;
            const long so = kof + s * 8;
            CP16(dstS + r * ROWB2 + s * 16,         srcA + (long)r * lda + so);
            CP16(dstS + ATIL2 + r * ROWB2 + s * 16, srcB + (long)r * ldb + so);
        }
        CPCOMMIT();
    };

    load_stage(0);
    if (NC > 1) load_stage(1);

    for (int c = 0; c < NC; c++) {
        if (c + 2 <= NC) { CPWAIT(1); } else { CPWAIT(0); }
        __syncthreads();
        if (c + 2 < NC) load_stage(c + 2);

        const uint32_t stb = sb + (uint32_t)(c % NSTAGE) * STAGE2;
        #pragma unroll
        for (int ks = 0; ks < 2; ks++) {
            uint32_t aF[2][4];
            const int rA   = wm * 32 + (lane & 15);
            const int colA = ks * 32 + ((lane >> 4) << 4);
            #pragma unroll
            for (int mf = 0; mf < 2; mf++)
                ldsm4(aF[mf], stb + (rA + mf * 16) * ROWB2 + colA);
            const int rB   = wn * 64 + ((lane >> 4) & 1) * 8 + (lane & 7);
            const int colB = ks * 32 + ((lane >> 3) & 1) * 16;
            #pragma unroll
            for (int g = 0; g < 4; g++) {
                uint32_t b4[4];
                ldsm4(b4, stb + ATIL2 + (rB + g * 16) * ROWB2 + colB);
                #pragma unroll
                for (int mf = 0; mf < 2; mf++) {
                    mma16816h(acc[mf][2*g],   aF[mf], b4);
                    mma16816h(acc[mf][2*g+1], aF[mf], b4 + 2);
                }
            }
        }
    }

    const long rbase = (long)blockIdx.y * 128 + wm * 32 + (lane >> 2);
    const int  gcol0 = blockIdx.x * 128;
    #pragma unroll
    for (int mf = 0; mf < 2; mf++)
        #pragma unroll
        for (int rh = 0; rh < 2; rh++) {
            const long r = rbase + mf * 16 + rh * 8;
            #pragma unroll
            for (int nf = 0; nf < 8; nf++) {
                const int col = gcol0 + wn * 64 + 2 * (lane & 3) + nf * 8;
                float v0 = acc[mf][nf][rh * 2 + 0];
                float v1 = acc[mf][nf][rh * 2 + 1];
                if (EPI == 0) {
                    if (bias) { v0 += bias[col]; v1 += bias[col + 1]; }
                    float2 f2; f2.x = v0; f2.y = v1;
                    *(float2*)(Cf + (long)bz * sC + r * N + col) = f2;
                } else {
                    __half2 hv; hv.x = __float2half(v0); hv.y = __float2half(v1);
                    *(__half2*)(Oz + (long)bz * sC + r * N + col) = hv;
                }
            }
        }
}

// ---------------------------------------------------------------------------
// Fused x prep: per batch, tile-transpose kernel that emits
//   xh/xl (bf16 hi/lo, [S,D] layout, coalesced) AND xt16 (fp16, [D,S] layout)
// Replaces split_x + transpose_h and removes the x16 intermediate buffer.
// grid (DD/32, SS/32, BB), block (32,8)
// ---------------------------------------------------------------------------
__global__ void split_x_t(const float* __restrict__ in,
                          __nv_bfloat16* __restrict__ oh, __nv_bfloat16* __restrict__ ol,
                          __half* __restrict__ ot)
{
    __shared__ float t[32][33];
    const long bIn = (long)blockIdx.z * SS * DD;
    const long bOt = (long)blockIdx.z * DD * SS;
    const int c0 = blockIdx.x * 32, rr0 = blockIdx.y * 32;
    const int tx = threadIdx.x, ty = threadIdx.y;
    #pragma unroll
    for (int k = 0; k < 32; k += 8) {
        const long idx = bIn + (long)(rr0 + ty + k) * DD + c0 + tx;
        float v = in[idx];
        t[ty + k][tx] = v;
        __nv_bfloat16 h = __float2bfloat16(v);
        oh[idx] = h;
        ol[idx] = __float2bfloat16(v - __bfloat162float(h));
    }
    __syncthreads();
    #pragma unroll
    for (int k = 0; k < 32; k += 8)
        ot[bOt + (long)(c0 + ty + k) * SS + rr0 + tx] = __float2half(t[tx][ty + k]);
}

// Merged Wq+Wk split: blockIdx.y selects the matrix (0=Wq, 1=Wk)
__global__ void split_w2(const float* __restrict__ Wq, const float* __restrict__ Wk,
                         __nv_bfloat16* __restrict__ qh, __nv_bfloat16* __restrict__ ql,
                         __nv_bfloat16* __restrict__ kh, __nv_bfloat16* __restrict__ kl,
                         int n4)
{
    int i = blockIdx.x * 256 + threadIdx.x;
    if (i >= n4) return;
    const float* in = blockIdx.y ? Wk : Wq;
    __nv_bfloat16* oh = blockIdx.y ? kh : qh;
    __nv_bfloat16* ol = blockIdx.y ? kl : ql;
    float4 v = ((const float4*)in)[i];
    __nv_bfloat16 h0 = __float2bfloat16(v.x), h1 = __float2bfloat16(v.y);
    __nv_bfloat16 h2 = __float2bfloat16(v.z), h3 = __float2bfloat16(v.w);
    __nv_bfloat162 hA; hA.x = h0; hA.y = h1;
    __nv_bfloat162 hB; hB.x = h2; hB.y = h3;
    __nv_bfloat162 lA, lB;
    lA.x = __float2bfloat16(v.x - __bfloat162float(h0));
    lA.y = __float2bfloat16(v.y - __bfloat162float(h1));
    lB.x = __float2bfloat16(v.z - __bfloat162float(h2));
    lB.y = __float2bfloat16(v.w - __bfloat162float(h3));
    ((__nv_bfloat162*)oh)[2*i]   = hA;
    ((__nv_bfloat162*)oh)[2*i+1] = hB;
    ((__nv_bfloat162*)ol)[2*i]   = lA;
    ((__nv_bfloat162*)ol)[2*i+1] = lB;
}

// MT partials (4) -> sum -> bf16 hi/lo
__global__ void mt_reduce_split(const float* __restrict__ parts, __nv_bfloat16* __restrict__ oh,
                                __nv_bfloat16* __restrict__ ol, int n4)
{
    int i = blockIdx.x * 256 + threadIdx.x;
    if (i < n4) {
        float4 s = ((const float4*)parts)[i];
        #pragma unroll
        for (int p = 1; p < 4; p++) {
            float4 t = ((const float4*)(parts + (size_t)p * DD * DD))[i];
            s.x += t.x; s.y += t.y; s.z += t.z; s.w += t.w;
        }
        __nv_bfloat16 h0 = __float2bfloat16(s.x), h1 = __float2bfloat16(s.y);
        __nv_bfloat16 h2 = __float2bfloat16(s.z), h3 = __float2bfloat16(s.w);
        __nv_bfloat162 hA; hA.x = h0; hA.y = h1;
        __nv_bfloat162 hB; hB.x = h2; hB.y = h3;
        __nv_bfloat162 lA, lB;
        lA.x = __float2bfloat16(s.x - __bfloat162float(h0));
        lA.y = __float2bfloat16(s.y - __bfloat162float(h1));
        lB.x = __float2bfloat16(s.z - __bfloat162float(h2));
        lB.y = __float2bfloat16(s.w - __bfloat162float(h3));
        ((__nv_bfloat162*)oh)[2*i]   = hA;
        ((__nv_bfloat162*)oh)[2*i+1] = hB;
        ((__nv_bfloat162*)ol)[2*i]   = lA;
        ((__nv_bfloat162*)ol)[2*i+1] = lB;
    }
}

// fp32 [R,C] -> fp16 [C,R] transpose (Wv -> Wv^T)
__global__ void transpose_f2h(const float* __restrict__ in, __half* __restrict__ out,
                              int R, int C)
{
    __shared__ float t[32][33];
    const int c0 = blockIdx.x * 32, rr0 = blockIdx.y * 32;
    const int tx = threadIdx.x, ty = threadIdx.y;
    #pragma unroll
    for (int k = 0; k < 32; k += 8)
        t[ty + k][tx] = in[(long)(rr0 + ty + k) * C + c0 + tx];
    __syncthreads();
    #pragma unroll
    for (int k = 0; k < 32; k += 8)
        out[(long)(c0 + ty + k) * R + rr0 + tx] = __float2half(t[tx][ty + k]);
}

// s0 = bq . bk
__global__ void s0_kernel(const float* __restrict__ bq, const float* __restrict__ bk,
                          float* __restrict__ s0)
{
    __shared__ float red[256];
    const int tid = threadIdx.x;
    float s = 0.f;
    for (int i = tid; i < DD; i += 256) s += bq[i] * bk[i];
    red[tid] = s; __syncthreads();
    #pragma unroll
    for (int k = 128; k > 0; k >>= 1) {
        if (tid < k) red[tid] += red[tid + k];
        __syncthreads();
    }
    if (tid == 0) s0[0] = red[0];
}

// cq = Wq bk, ck = Wk bq (warp per output element)
__global__ void gemv_cqck(const float* __restrict__ Wq, const float* __restrict__ Wk,
                          const float* __restrict__ bq, const float* __restrict__ bk,
                          float* __restrict__ cq, float* __restrict__ ck)
{
    const int lane = threadIdx.x & 31, warp = threadIdx.x >> 5;
    const int d = blockIdx.x * 8 + warp;
    float a1 = 0.f, a2 = 0.f;
    for (int i = lane; i < DD; i += 32) {
        a1 += Wq[(long)d * DD + i] * bk[i];
        a2 += Wk[(long)d * DD + i] * bq[i];
    }
    #pragma unroll
    for (int o = 16; o > 0; o >>= 1) {
        a1 += __shfl_xor_sync(0xffffffff, a1, o);
        a2 += __shfl_xor_sync(0xffffffff, a2, o);
    }
    if (lane == 0) { cq[d] = a1; ck[d] = a2; }
}

// u = x cq, w = x ck (warp per row)
__global__ void gemv_uw(const float* __restrict__ x, const float* __restrict__ cq,
                        const float* __restrict__ ck, float* __restrict__ u, float* __restrict__ w)
{
    const int lane = threadIdx.x & 31, warp = threadIdx.x >> 5;
    const long r = (long)blockIdx.x * 8 + warp;
    float a1 = 0.f, a2 = 0.f;
    for (int d = lane; d < DD; d += 32) {
        float xv = x[r * DD + d];
        a1 += xv * cq[d];
        a2 += xv * ck[d];
    }
    #pragma unroll
    for (int o = 16; o > 0; o >>= 1) {
        a1 += __shfl_xor_sync(0xffffffff, a1, o);
        a2 += __shfl_xor_sync(0xffffffff, a2, o);
    }
    if (lane == 0) { u[r] = a1; w[r] = a2; }
}

// ---------------------------------------------------------------------------
// Row softmax + entropy; logits = (raw + u_r + w_c + s0)/(8*temp); probs fp16.
// Warp-shuffle reductions, fused (l,t) cross-warp stage: 4 barriers/block.
// ---------------------------------------------------------------------------
__global__ void softmax_ent(const float* __restrict__ P, const float* __restrict__ u,
                            const float* __restrict__ w, const float* __restrict__ s0,
                            __half* __restrict__ P16, float* __restrict__ ent,
                            const float* __restrict__ temp)
{
    __shared__ float sred[20];
    const float* p = P + (long)blockIdx.x * SS;
    __half* o = P16 + (long)blockIdx.x * SS;
    const int tid = threadIdx.x, lane = tid & 31, wid = tid >> 5;
    const float scale = 1.0f / (8.0f * temp[0]);
    const float ub = u[blockIdx.x] + s0[0];
    const float* wb = w + (blockIdx.x / SS) * SS;

    float v[8];
    #pragma unroll
    for (int j = 0; j < 8; j++) {
        const int c = tid + j * 256;
        v[j] = (p[c] + ub + wb[c]) * scale;
    }

    float m = v[0];
    #pragma unroll
    for (int j = 1; j < 8; j++) m = fmaxf(m, v[j]);
    #pragma unroll
    for (int s = 16; s > 0; s >>= 1) m = fmaxf(m, __shfl_xor_sync(0xffffffff, m, s));
    if (lane == 0) sred[wid] = m;
    __syncthreads();
    if (wid == 0) {
        float t2 = (lane < 8) ? sred[lane] : -3.4e38f;
        #pragma unroll
        for (int s = 4; s > 0; s >>= 1) t2 = fmaxf(t2, __shfl_xor_sync(0xffffffff, t2, s));
        if (lane == 0) sred[16] = t2;
    }
    __syncthreads();
    m = sred[16];

    float e[8], l = 0.f, t = 0.f;
    #pragma unroll
    for (int j = 0; j < 8; j++) {
        e[j] = __expf(v[j] - m);
        l += e[j];
        t += e[j] * v[j];
    }
    #pragma unroll
    for (int s = 16; s > 0; s >>= 1) {
        l += __shfl_xor_sync(0xffffffff, l, s);
        t += __shfl_xor_sync(0xffffffff, t, s);
    }
    if (lane == 0) { sred[wid] = l; sred[8 + wid] = t; }
    __syncthreads();
    if (wid == 0) {
        float a = (lane < 8) ? sred[lane] : 0.f;
        float b = (lane < 8) ? sred[8 + lane] : 0.f;
        #pragma unroll
        for (int s = 4; s > 0; s >>= 1) {
            a += __shfl_xor_sync(0xffffffff, a, s);
            b += __shfl_xor_sync(0xffffffff, b, s);
        }
        if (lane == 0) { sred[17] = a; sred[18] = b; }
    }
    __syncthreads();
    l = sred[17]; t = sred[18];

    const float inv = 1.0f / l;
    #pragma unroll
    for (int j = 0; j < 8; j++)
        o[tid + j * 256] = __float2half(e[j] * inv);

    if (tid == 0) ent[blockIdx.x] = m + logf(l) - t * inv;
}

__global__ void ent_reduce(const float* __restrict__ ent, float* __restrict__ out)
{
    __shared__ float red[256];
    const int tid = threadIdx.x;
    float s = 0.f;
    for (int i = tid; i < MS; i += 256) s += ent[i];
    red[tid] = s; __syncthreads();
    #pragma unroll
    for (int k = 128; k > 0; k >>= 1) {
        if (tid < k) red[tid] += red[tid + k];
        __syncthreads();
    }
    if (tid == 0) out[0] = red[0] / (float)MS;
}

// ---------------------------------------------------------------------------
extern "C" void kernel_launch(void* const* d_in, const int* in_sizes, int n_in,
                              void* d_out, int out_size)
{
    const float* x    = (const float*)d_in[0];
    const float* Wq   = (const float*)d_in[1];
    const float* bq   = (const float*)d_in[2];
    const float* Wk   = (const float*)d_in[3];
    const float* bk   = (const float*)d_in[4];
    const float* Wv   = (const float*)d_in[5];
    const float* bv   = (const float*)d_in[6];
    const float* temp = (const float*)d_in[7];
    float* out = (float*)d_out;

    __nv_bfloat16 *xh, *xl, *wqh, *wql, *wkh, *wkl, *mth, *mtl, *yh, *yl;
    __half *xt16, *wvt16, *p16, *z16;
    float *mtp, *p, *cq, *ck, *u, *w, *s0, *ent;
    cudaGetSymbolAddress((void**)&xh,  g_xh);   cudaGetSymbolAddress((void**)&xl,  g_xl);
    cudaGetSymbolAddress((void**)&xt16, g_xt16);
    cudaGetSymbolAddress((void**)&wqh, g_wqh);  cudaGetSymbolAddress((void**)&wql, g_wql);
    cudaGetSymbolAddress((void**)&wkh, g_wkh);  cudaGetSymbolAddress((void**)&wkl, g_wkl);
    cudaGetSymbolAddress((void**)&wvt16, g_wvt16);
    cudaGetSymbolAddress((void**)&mtp, g_mtp);
    cudaGetSymbolAddress((void**)&mth, g_mth);  cudaGetSymbolAddress((void**)&mtl, g_mtl);
    cudaGetSymbolAddress((void**)&yh,  g_yh);   cudaGetSymbolAddress((void**)&yl,  g_yl);
    cudaGetSymbolAddress((void**)&p,   g_p);    cudaGetSymbolAddress((void**)&p16, g_p16);
    cudaGetSymbolAddress((void**)&z16, g_z16);
    cudaGetSymbolAddress((void**)&cq,  g_cq);   cudaGetSymbolAddress((void**)&ck,  g_ck);
    cudaGetSymbolAddress((void**)&u,   g_u);    cudaGetSymbolAddress((void**)&w,   g_w);
    cudaGetSymbolAddress((void**)&s0,  g_s0);   cudaGetSymbolAddress((void**)&ent, g_ent);

    cudaFuncSetAttribute(mma_gemm<0>,    cudaFuncAttributeMaxDynamicSharedMemorySize, SMEMB);
    cudaFuncSetAttribute(mma_gemm<2>,    cudaFuncAttributeMaxDynamicSharedMemorySize, SMEMB);
    cudaFuncSetAttribute(mma_gemm_h1<0>, cudaFuncAttributeMaxDynamicSharedMemorySize, SMEM2);
    cudaFuncSetAttribute(mma_gemm_h1<1>, cudaFuncAttributeMaxDynamicSharedMemorySize, SMEM2);

    dim3 tb(32, 8);

    // 1) fused x prep: xh/xl (bf16 pair) + xt16 (fp16 transposed) in one pass
    split_x_t<<<dim3(DD/32, SS/32, BB), tb>>>(x, xh, xl, xt16);
    // Wq & Wk splits merged into one launch; Wv -> fp16 transposed
    {
        dim3 g2((DD*DD/4 + 255)/256, 2, 1);
        split_w2<<<g2, 256>>>(Wq, Wk, wqh, wql, wkh, wkl, DD*DD/4);
    }
    transpose_f2h<<<dim3(DD/32, DD/32, 1), tb>>>(Wv, wvt16, DD, DD);

    // bias rank-1 terms (exact fp32; zeros in this dataset but handled generally)
    s0_kernel<<<1, 256>>>(bq, bk, s0);
    gemv_cqck<<<DD/8, 256>>>(Wq, Wk, bq, bk, cq, ck);
    gemv_uw<<<MS/8, 256>>>(x, cq, ck, u, w);

    // 2) M^T = Wk Wq^T, K-split over 4 partials, then reduce+split to bf16
    mma_gemm<0><<<dim3(DD/128, DD/128, 4), 256, SMEMB>>>(
        wkh, wkl, wqh, wql, mtp, nullptr, nullptr,
        DD, 256, DD, DD, 256, 256, (long)DD*DD);
    mt_reduce_split<<<(DD*DD/4 + 255)/256, 256>>>(mtp, mth, mtl, DD*DD/4);

    // 3) y = x M  (NT vs M^T) -> bf16 hi/lo
    mma_gemm<2><<<dim3(DD/128, MS/128, 1), 256, SMEMB>>>(
        xh, xl, mth, mtl, nullptr, yh, yl,
        DD, DD, DD, DD, 0, 0, 0);

    // 4) scores = y x^T per batch -> fp32
    mma_gemm<0><<<dim3(SS/128, SS/128, BB), 256, SMEMB>>>(
        yh, yl, xh, xl, p, nullptr, nullptr,
        SS, DD, DD, DD, (long)SS*DD, (long)SS*DD, (long)SS*SS);

    // 5) softmax + entropy (adds bias rank-1 terms) -> p16
    softmax_ent<<<MS, 256>>>(p, u, w, s0, p16, ent, temp);

    // 6) z = p x per batch (fp16) -> fp16
    mma_gemm_h1<1><<<dim3(DD/128, SS/128, BB), 256, SMEM2>>>(
        p16, xt16, nullptr, z16, nullptr,
        DD, SS, SS, SS, (long)SS*SS, (long)DD*SS, (long)SS*DD);

    // 7) out = z Wv + bv (fp16 MMA, fp32 out)
    mma_gemm_h1<0><<<dim3(DD/128, MS/128, 1), 256, SMEM2>>>(
        z16, wvt16, out, nullptr, bv,
        DD, DD, DD, DD, 0, 0, 0);

    // 8) entropy mean scalar
    ent_reduce<<<1, 256>>>(ent, out + OUT_ELEMS);
}

// round 16
// speedup vs baseline: 2.6167x; 1.0062x over previous
#include <cuda_runtime.h>
#include <cuda_bf16.h>
#include <cuda_fp16.h>
#include <math.h>
#include <stdint.h>

// Problem dims (fixed)
#define BB 4
#define SS 2048
#define DD 1024
#define MS (BB*SS)          // 8192 rows total
#define OUT_ELEMS (MS*DD)

// --- bf16 split GEMM smem geometry: rows hold hi(64B)|lo(64B), stride 144B ---
#define ROWB   144
#define ATILEB (128*ROWB)
#define STAGEB (2*ATILEB)              // A + B tile = 36864 B
#define NSTAGE 3
#define SMEMB  (NSTAGE*STAGEB)         // 110592 B -> 2 CTAs/SM

// --- fp16 single GEMM smem geometry: rows 64B data + 16B pad -> 80B ---
#define ROWB2   80
#define ATIL2   (128*ROWB2)
#define STAGE2  (2*ATIL2)              // 20480 B
#define SMEM2   (NSTAGE*STAGE2)        // 61440 B

// ---------------------------------------------------------------------------
// PTX helpers (sm_80-level only: cp.async, ldmatrix, mma.sync)
// ---------------------------------------------------------------------------
__device__ __forceinline__ uint32_t smem_u32(const void* p) {
    uint32_t a;
    asm("{ .reg .u64 t; cvta.to.shared.u64 t, %1; cvt.u32.u64 %0, t; }" : "=r"(a) : "l"(p));
    return a;
}
#define CP16(d, s) asm volatile("cp.async.cg.shared.global [%0], [%1], 16;" :: "r"(d), "l"(s))
#define CPCOMMIT() asm volatile("cp.async.commit_group;" ::: "memory")
#define CPWAIT(n)  asm volatile("cp.async.wait_group %0;" :: "n"(n) : "memory")

__device__ __forceinline__ void ldsm4(uint32_t* r, uint32_t a) {
    asm volatile("ldmatrix.sync.aligned.m8n8.x4.shared.b16 {%0,%1,%2,%3}, [%4];"
                 : "=r"(r[0]), "=r"(r[1]), "=r"(r[2]), "=r"(r[3]) : "r"(a));
}
__device__ __forceinline__ void mma16816(float* c, const uint32_t* a, const uint32_t* b) {
    asm volatile("mma.sync.aligned.m16n8k16.row.col.f32.bf16.bf16.f32 "
                 "{%0,%1,%2,%3}, {%4,%5,%6,%7}, {%8,%9}, {%0,%1,%2,%3};"
                 : "+f"(c[0]), "+f"(c[1]), "+f"(c[2]), "+f"(c[3])
                 : "r"(a[0]), "r"(a[1]), "r"(a[2]), "r"(a[3]), "r"(b[0]), "r"(b[1]));
}
__device__ __forceinline__ void mma16816h(float* c, const uint32_t* a, const uint32_t* b) {
    asm volatile("mma.sync.aligned.m16n8k16.row.col.f32.f16.f16.f32 "
                 "{%0,%1,%2,%3}, {%4,%5,%6,%7}, {%8,%9}, {%0,%1,%2,%3};"
                 : "+f"(c[0]), "+f"(c[1]), "+f"(c[2]), "+f"(c[3])
                 : "r"(a[0]), "r"(a[1]), "r"(a[2]), "r"(a[3]), "r"(b[0]), "r"(b[1]));
}

// ---------------------------------------------------------------------------
// Static scratch (allocation-free rule)
// ---------------------------------------------------------------------------
__device__ __align__(256) __nv_bfloat16 g_xh[MS*DD], g_xl[MS*DD];
__device__ __align__(256) __half         g_xt16[MS*DD];                 // per-batch x^T fp16
__device__ __align__(256) __nv_bfloat16 g_wqh[DD*DD], g_wql[DD*DD];
__device__ __align__(256) __nv_bfloat16 g_wkh[DD*DD], g_wkl[DD*DD];
__device__ __align__(256) __half         g_wvt16[DD*DD];                 // Wv^T fp16
__device__ __align__(256) float          g_mtp[4*DD*DD];                 // M^T K-split partials
__device__ __align__(256) __nv_bfloat16 g_mth[DD*DD], g_mtl[DD*DD];     // M^T = Wk Wq^T
__device__ __align__(256) __nv_bfloat16 g_yh[MS*DD], g_yl[MS*DD];       // y = x M
__device__ __align__(256) float          g_p[(size_t)BB*SS*SS];
__device__ __align__(256) __half         g_p16[(size_t)BB*SS*SS];
__device__ __align__(256) __half         g_z16[MS*DD];                   // z = p x
__device__ __align__(256) float          g_cq[DD], g_ck[DD], g_u[MS], g_w[MS], g_s0[1];
__device__ __align__(256) float          g_ent[MS];

// ---------------------------------------------------------------------------
// bf16 split GEMM via mma.sync:
//   C[M,N] = (Ah+Al)[.,K] x (Bh+Bl)[.,K]^T   (3 MMAs: hh + hl + lh)
// CTA tile 128x128, K-chunk 32, 256 threads = 8 warps (4 M x 2 N),
// 3-stage cp.async ring, ONE barrier/chunk, 2 CTAs/SM.
// EPI 0: fp32 store.  EPI 2: bf16 hi/lo split store (Oh/Ol, row stride N).
// ---------------------------------------------------------------------------
template<int EPI>
__global__ __launch_bounds__(256, 2)
void mma_gemm(const __nv_bfloat16* __restrict__ Ah, const __nv_bfloat16* __restrict__ Al,
              const __nv_bfloat16* __restrict__ Bh, const __nv_bfloat16* __restrict__ Bl,
              float* __restrict__ Cf, __nv_bfloat16* __restrict__ Oh, __nv_bfloat16* __restrict__ Ol,
              int N, int K, int lda, int ldb, long sA, long sB, long sC)
{
    extern __shared__ char sm[];
    const uint32_t sb = smem_u32(sm);
    const int tid = threadIdx.x, lane = tid & 31, warp = tid >> 5;
    const int wm = warp & 3, wn = warp >> 2;     // 4 M-warps x 2 N-warps
    const int bz = blockIdx.z;

    const __nv_bfloat16* srcA[2] = {
        Ah + (long)bz * sA + (long)blockIdx.y * 128 * lda,
        Al + (long)bz * sA + (long)blockIdx.y * 128 * lda };
    const __nv_bfloat16* srcB[2] = {
        Bh + (long)bz * sB + (long)blockIdx.x * 128 * ldb,
        Bl + (long)bz * sB + (long)blockIdx.x * 128 * ldb };

    float acc[2][8][4];
    #pragma unroll
    for (int a = 0; a < 2; a++)
        #pragma unroll
        for (int b = 0; b < 8; b++)
            #pragma unroll
            for (int c = 0; c < 4; c++) acc[a][b][c] = 0.f;

    const int NC = K >> 5;

    auto load_stage = [&](int c) {
        const uint32_t dstS = sb + (uint32_t)(c % NSTAGE) * STAGEB;
        const long kof = (long)c * 32;
        #pragma unroll
        for (int p = 0; p < 4; p++) {
            const int u = tid + p * 256;
            const int r = u >> 3, seg = u & 7;
            const int hl = seg >> 2;
            const long so = kof + (seg & 3) * 8;
            CP16(dstS + r * ROWB + seg * 16,          srcA[hl] + (long)r * lda + so);
            CP16(dstS + ATILEB + r * ROWB + seg * 16, srcB[hl] + (long)r * ldb + so);
        }
        CPCOMMIT();
    };

    load_stage(0);
    if (NC > 1) load_stage(1);

    for (int c = 0; c < NC; c++) {
        if (c + 2 <= NC) { CPWAIT(1); } else { CPWAIT(0); }
        __syncthreads();
        if (c + 2 < NC) load_stage(c + 2);

        const uint32_t stb = sb + (uint32_t)(c % NSTAGE) * STAGEB;
        #pragma unroll
        for (int ks = 0; ks < 2; ks++) {
            uint32_t aHi[2][4], aLo[2][4];
            const int rA   = wm * 32 + (lane & 15);
            const int colA = ks * 32 + ((lane >> 4) << 4);
            #pragma unroll
            for (int mf = 0; mf < 2; mf++) {
                const uint32_t ad = stb + (rA + mf * 16) * ROWB + colA;
                ldsm4(aHi[mf], ad);
                ldsm4(aLo[mf], ad + 64);
            }
            const int rB   = wn * 64 + ((lane >> 4) & 1) * 8 + (lane & 7);
            const int colB = ks * 32 + ((lane >> 3) & 1) * 16;
            #pragma unroll
            for (int g = 0; g < 4; g++) {
                uint32_t bh4[4], bl4[4];
                const uint32_t bd = stb + ATILEB + (rB + g * 16) * ROWB + colB;
                ldsm4(bh4, bd);
                ldsm4(bl4, bd + 64);
                #pragma unroll
                for (int mf = 0; mf < 2; mf++) {
                    mma16816(acc[mf][2*g],   aHi[mf], bh4);
                    mma16816(acc[mf][2*g],   aHi[mf], bl4);
                    mma16816(acc[mf][2*g],   aLo[mf], bh4);
                    mma16816(acc[mf][2*g+1], aHi[mf], bh4 + 2);
                    mma16816(acc[mf][2*g+1], aHi[mf], bl4 + 2);
                    mma16816(acc[mf][2*g+1], aLo[mf], bh4 + 2);
                }
            }
        }
    }

    // ---- epilogue ----
    const long rbase = (long)blockIdx.y * 128 + wm * 32 + (lane >> 2);
    const int  gcol0 = blockIdx.x * 128;

    #pragma unroll
    for (int mf = 0; mf < 2; mf++)
        #pragma unroll
        for (int rh = 0; rh < 2; rh++) {
            const long r = rbase + mf * 16 + rh * 8;
            #pragma unroll
            for (int nf = 0; nf < 8; nf++) {
                const int col = gcol0 + wn * 64 + 2 * (lane & 3) + nf * 8;
                float v0 = acc[mf][nf][rh * 2 + 0];
                float v1 = acc[mf][nf][rh * 2 + 1];
                if (EPI == 0) {
                    float2 f2; f2.x = v0; f2.y = v1;
                    *(float2*)(Cf + (long)bz * sC + r * N + col) = f2;
                } else {
                    __nv_bfloat16 h0 = __float2bfloat16(v0);
                    __nv_bfloat16 h1 = __float2bfloat16(v1);
                    __nv_bfloat162 hh; hh.x = h0; hh.y = h1;
                    __nv_bfloat162 ll;
                    ll.x = __float2bfloat16(v0 - __bfloat162float(h0));
                    ll.y = __float2bfloat16(v1 - __bfloat162float(h1));
                    *(__nv_bfloat162*)(Oh + (long)bz * sC + r * N + col) = hh;
                    *(__nv_bfloat162*)(Ol + (long)bz * sC + r * N + col) = ll;
                }
            }
        }
}

// ---------------------------------------------------------------------------
// fp16 single-term GEMM: C[M,N] = A[.,K] x B[.,K]^T, fp32 accum.
// EPI 0: fp32 store + bias.  EPI 1: fp16 store.
// ---------------------------------------------------------------------------
template<int EPI>
__global__ __launch_bounds__(256, 2)
void mma_gemm_h1(const __half* __restrict__ A, const __half* __restrict__ B,
                 float* __restrict__ Cf, __half* __restrict__ Oz,
                 const float* __restrict__ bias,
                 int N, int K, int lda, int ldb, long sA, long sB, long sC)
{
    extern __shared__ char sm[];
    const uint32_t sb = smem_u32(sm);
    const int tid = threadIdx.x, lane = tid & 31, warp = tid >> 5;
    const int wm = warp & 3, wn = warp >> 2;
    const int bz = blockIdx.z;

    const __half* srcA = A + (long)bz * sA + (long)blockIdx.y * 128 * lda;
    const __half* srcB = B + (long)bz * sB + (long)blockIdx.x * 128 * ldb;

    float acc[2][8][4];
    #pragma unroll
    for (int a = 0; a < 2; a++)
        #pragma unroll
        for (int b = 0; b < 8; b++)
            #pragma unroll
            for (int c = 0; c < 4; c++) acc[a][b][c] = 0.f;

    const int NC = K >> 5;

    auto load_stage = [&](int c) {
        const uint32_t dstS = sb + (uint32_t)(c % NSTAGE) * STAGE2;
        const long kof = (long)c * 32;
        #pragma unroll
        for (int p = 0; p < 2; p++) {
            const int u = tid + p * 256;
            const int r = u >> 2, s = u & 3;
            const long so = kof + s * 8;
            CP16(dstS + r * ROWB2 + s * 16,         srcA + (long)r * lda + so);
            CP16(dstS + ATIL2 + r * ROWB2 + s * 16, srcB + (long)r * ldb + so);
        }
        CPCOMMIT();
    };

    load_stage(0);
    if (NC > 1) load_stage(1);

    for (int c = 0; c < NC; c++) {
        if (c + 2 <= NC) { CPWAIT(1); } else { CPWAIT(0); }
        __syncthreads();
        if (c + 2 < NC) load_stage(c + 2);

        const uint32_t stb = sb + (uint32_t)(c % NSTAGE) * STAGE2;
        #pragma unroll
        for (int ks = 0; ks < 2; ks++) {
            uint32_t aF[2][4];
            const int rA   = wm * 32 + (lane & 15);
            const int colA = ks * 32 + ((lane >> 4) << 4);
            #pragma unroll
            for (int mf = 0; mf < 2; mf++)
                ldsm4(aF[mf], stb + (rA + mf * 16) * ROWB2 + colA);
            const int rB   = wn * 64 + ((lane >> 4) & 1) * 8 + (lane & 7);
            const int colB = ks * 32 + ((lane >> 3) & 1) * 16;
            #pragma unroll
            for (int g = 0; g < 4; g++) {
                uint32_t b4[4];
                ldsm4(b4, stb + ATIL2 + (rB + g * 16) * ROWB2 + colB);
                #pragma unroll
                for (int mf = 0; mf < 2; mf++) {
                    mma16816h(acc[mf][2*g],   aF[mf], b4);
                    mma16816h(acc[mf][2*g+1], aF[mf], b4 + 2);
                }
            }
        }
    }

    const long rbase = (long)blockIdx.y * 128 + wm * 32 + (lane >> 2);
    const int  gcol0 = blockIdx.x * 128;
    #pragma unroll
    for (int mf = 0; mf < 2; mf++)
        #pragma unroll
        for (int rh = 0; rh < 2; rh++) {
            const long r = rbase + mf * 16 + rh * 8;
            #pragma unroll
            for (int nf = 0; nf < 8; nf++) {
                const int col = gcol0 + wn * 64 + 2 * (lane & 3) + nf * 8;
                float v0 = acc[mf][nf][rh * 2 + 0];
                float v1 = acc[mf][nf][rh * 2 + 1];
                if (EPI == 0) {
                    if (bias) { v0 += bias[col]; v1 += bias[col + 1]; }
                    float2 f2; f2.x = v0; f2.y = v1;
                    *(float2*)(Cf + (long)bz * sC + r * N + col) = f2;
                } else {
                    __half2 hv; hv.x = __float2half(v0); hv.y = __float2half(v1);
                    *(__half2*)(Oz + (long)bz * sC + r * N + col) = hv;
                }
            }
        }
}

// ---------------------------------------------------------------------------
// Fused x prep: per batch, tile-transpose kernel that emits
//   xh/xl (bf16 hi/lo, [S,D] layout, coalesced) AND xt16 (fp16, [D,S] layout)
// grid (DD/32, SS/32, BB), block (32,8)
// ---------------------------------------------------------------------------
__global__ void split_x_t(const float* __restrict__ in,
                          __nv_bfloat16* __restrict__ oh, __nv_bfloat16* __restrict__ ol,
                          __half* __restrict__ ot)
{
    __shared__ float t[32][33];
    const long bIn = (long)blockIdx.z * SS * DD;
    const long bOt = (long)blockIdx.z * DD * SS;
    const int c0 = blockIdx.x * 32, rr0 = blockIdx.y * 32;
    const int tx = threadIdx.x, ty = threadIdx.y;
    #pragma unroll
    for (int k = 0; k < 32; k += 8) {
        const long idx = bIn + (long)(rr0 + ty + k) * DD + c0 + tx;
        float v = in[idx];
        t[ty + k][tx] = v;
        __nv_bfloat16 h = __float2bfloat16(v);
        oh[idx] = h;
        ol[idx] = __float2bfloat16(v - __bfloat162float(h));
    }
    __syncthreads();
    #pragma unroll
    for (int k = 0; k < 32; k += 8)
        ot[bOt + (long)(c0 + ty + k) * SS + rr0 + tx] = __float2half(t[tx][ty + k]);
}

// ---------------------------------------------------------------------------
// Fused weight prep. grid (32, 32, 3), block (32,8):
//   z=0: Wq elementwise bf16 hi/lo split (tile region)
//   z=1: Wk elementwise bf16 hi/lo split
//   z=2: Wv transpose -> fp16 Wv^T
// ---------------------------------------------------------------------------
__global__ void prep_w(const float* __restrict__ Wq, const float* __restrict__ Wk,
                       const float* __restrict__ Wv,
                       __nv_bfloat16* __restrict__ qh, __nv_bfloat16* __restrict__ ql,
                       __nv_bfloat16* __restrict__ kh, __nv_bfloat16* __restrict__ kl,
                       __half* __restrict__ wvt)
{
    const int c0 = blockIdx.x * 32, rr0 = blockIdx.y * 32;
    const int tx = threadIdx.x, ty = threadIdx.y;
    if (blockIdx.z < 2) {
        const float* in = blockIdx.z ? Wk : Wq;
        __nv_bfloat16* oh = blockIdx.z ? kh : qh;
        __nv_bfloat16* ol = blockIdx.z ? kl : ql;
        #pragma unroll
        for (int k = 0; k < 32; k += 8) {
            const long idx = (long)(rr0 + ty + k) * DD + c0 + tx;
            float v = in[idx];
            __nv_bfloat16 h = __float2bfloat16(v);
            oh[idx] = h;
            ol[idx] = __float2bfloat16(v - __bfloat162float(h));
        }
    } else {
        __shared__ float t[32][33];
        #pragma unroll
        for (int k = 0; k < 32; k += 8)
            t[ty + k][tx] = Wv[(long)(rr0 + ty + k) * DD + c0 + tx];
        __syncthreads();
        #pragma unroll
        for (int k = 0; k < 32; k += 8)
            wvt[(long)(c0 + ty + k) * DD + rr0 + tx] = __float2half(t[tx][ty + k]);
    }
}

// MT partials (4) -> sum -> bf16 hi/lo
__global__ void mt_reduce_split(const float* __restrict__ parts, __nv_bfloat16* __restrict__ oh,
                                __nv_bfloat16* __restrict__ ol, int n4)
{
    int i = blockIdx.x * 256 + threadIdx.x;
    if (i < n4) {
        float4 s = ((const float4*)parts)[i];
        #pragma unroll
        for (int p = 1; p < 4; p++) {
            float4 t = ((const float4*)(parts + (size_t)p * DD * DD))[i];
            s.x += t.x; s.y += t.y; s.z += t.z; s.w += t.w;
        }
        __nv_bfloat16 h0 = __float2bfloat16(s.x), h1 = __float2bfloat16(s.y);
        __nv_bfloat16 h2 = __float2bfloat16(s.z), h3 = __float2bfloat16(s.w);
        __nv_bfloat162 hA; hA.x = h0; hA.y = h1;
        __nv_bfloat162 hB; hB.x = h2; hB.y = h3;
        __nv_bfloat162 lA, lB;
        lA.x = __float2bfloat16(s.x - __bfloat162float(h0));
        lA.y = __float2bfloat16(s.y - __bfloat162float(h1));
        lB.x = __float2bfloat16(s.z - __bfloat162float(h2));
        lB.y = __float2bfloat16(s.w - __bfloat162float(h3));
        ((__nv_bfloat162*)oh)[2*i]   = hA;
        ((__nv_bfloat162*)oh)[2*i+1] = hB;
        ((__nv_bfloat162*)ol)[2*i]   = lA;
        ((__nv_bfloat162*)ol)[2*i+1] = lB;
    }
}

// cq = Wq bk, ck = Wk bq (warp per output element); block 0 warp 0 also s0=bq.bk
__global__ void gemv_cqck(const float* __restrict__ Wq, const float* __restrict__ Wk,
                          const float* __restrict__ bq, const float* __restrict__ bk,
                          float* __restrict__ cq, float* __restrict__ ck,
                          float* __restrict__ s0)
{
    const int lane = threadIdx.x & 31, warp = threadIdx.x >> 5;
    const int d = blockIdx.x * 8 + warp;
    float a1 = 0.f, a2 = 0.f;
    for (int i = lane; i < DD; i += 32) {
        a1 += Wq[(long)d * DD + i] * bk[i];
        a2 += Wk[(long)d * DD + i] * bq[i];
    }
    #pragma unroll
    for (int o = 16; o > 0; o >>= 1) {
        a1 += __shfl_xor_sync(0xffffffff, a1, o);
        a2 += __shfl_xor_sync(0xffffffff, a2, o);
    }
    if (lane == 0) { cq[d] = a1; ck[d] = a2; }
    if (blockIdx.x == 0 && warp == 0) {
        float s = 0.f;
        for (int i = lane; i < DD; i += 32) s += bq[i] * bk[i];
        #pragma unroll
        for (int o = 16; o > 0; o >>= 1) s += __shfl_xor_sync(0xffffffff, s, o);
        if (lane == 0) s0[0] = s;
    }
}

// u = x cq, w = x ck (warp per row)
__global__ void gemv_uw(const float* __restrict__ x, const float* __restrict__ cq,
                        const float* __restrict__ ck, float* __restrict__ u, float* __restrict__ w)
{
    const int lane = threadIdx.x & 31, warp = threadIdx.x >> 5;
    const long r = (long)blockIdx.x * 8 + warp;
    float a1 = 0.f, a2 = 0.f;
    for (int d = lane; d < DD; d += 32) {
        float xv = x[r * DD + d];
        a1 += xv * cq[d];
        a2 += xv * ck[d];
    }
    #pragma unroll
    for (int o = 16; o > 0; o >>= 1) {
        a1 += __shfl_xor_sync(0xffffffff, a1, o);
        a2 += __shfl_xor_sync(0xffffffff, a2, o);
    }
    if (lane == 0) { u[r] = a1; w[r] = a2; }
}

// ---------------------------------------------------------------------------
// Row softmax + entropy; logits = (raw + u_r + w_c + s0)/(8*temp); probs fp16.
// float4 vectorized (each thread owns a contiguous 8-elem span),
// warp-shuffle reductions, fused (l,t) cross-warp stage.
// ---------------------------------------------------------------------------
__global__ void softmax_ent(const float* __restrict__ P, const float* __restrict__ u,
                            const float* __restrict__ w, const float* __restrict__ s0,
                            __half* __restrict__ P16, float* __restrict__ ent,
                            const float* __restrict__ temp)
{
    __shared__ float sred[20];
    const float* p = P + (long)blockIdx.x * SS;
    __half* o = P16 + (long)blockIdx.x * SS;
    const int tid = threadIdx.x, lane = tid & 31, wid = tid >> 5;
    const float scale = 1.0f / (8.0f * temp[0]);
    const float ub = u[blockIdx.x] + s0[0];
    const float* wb = w + (blockIdx.x / SS) * SS;

    float v[8];
    {
        const int c8 = tid * 8;
        float4 p0 = ((const float4*)(p + c8))[0];
        float4 p1 = ((const float4*)(p + c8))[1];
        float4 w0 = ((const float4*)(wb + c8))[0];
        float4 w1 = ((const float4*)(wb + c8))[1];
        v[0] = (p0.x + ub + w0.x) * scale;
        v[1] = (p0.y + ub + w0.y) * scale;
        v[2] = (p0.z + ub + w0.z) * scale;
        v[3] = (p0.w + ub + w0.w) * scale;
        v[4] = (p1.x + ub + w1.x) * scale;
        v[5] = (p1.y + ub + w1.y) * scale;
        v[6] = (p1.z + ub + w1.z) * scale;
        v[7] = (p1.w + ub + w1.w) * scale;
    }

    float m = v[0];
    #pragma unroll
    for (int j = 1; j < 8; j++) m = fmaxf(m, v[j]);
    #pragma unroll
    for (int s = 16; s > 0; s >>= 1) m = fmaxf(m, __shfl_xor_sync(0xffffffff, m, s));
    if (lane == 0) sred[wid] = m;
    __syncthreads();
    if (wid == 0) {
        float t2 = (lane < 8) ? sred[lane] : -3.4e38f;
        #pragma unroll
        for (int s = 4; s > 0; s >>= 1) t2 = fmaxf(t2, __shfl_xor_sync(0xffffffff, t2, s));
        if (lane == 0) sred[16] = t2;
    }
    __syncthreads();
    m = sred[16];

    float e[8], l = 0.f, t = 0.f;
    #pragma unroll
    for (int j = 0; j < 8; j++) {
        e[j] = __expf(v[j] - m);
        l += e[j];
        t += e[j] * v[j];
    }
    #pragma unroll
    for (int s = 16; s > 0; s >>= 1) {
        l += __shfl_xor_sync(0xffffffff, l, s);
        t += __shfl_xor_sync(0xffffffff, t, s);
    }
    if (lane == 0) { sred[wid] = l; sred[8 + wid] = t; }
    __syncthreads();
    if (wid == 0) {
        float a = (lane < 8) ? sred[lane] : 0.f;
        float b = (lane < 8) ? sred[8 + lane] : 0.f;
        #pragma unroll
        for (int s = 4; s > 0; s >>= 1) {
            a += __shfl_xor_sync(0xffffffff, a, s);
            b += __shfl_xor_sync(0xffffffff, b, s);
        }
        if (lane == 0) { sred[17] = a; sred[18] = b; }
    }
    __syncthreads();
    l = sred[17]; t = sred[18];

    const float inv = 1.0f / l;
    {
        __half2* o2 = (__half2*)(o + tid * 8);
        #pragma unroll
        for (int j = 0; j < 4; j++) {
            __half2 hv;
            hv.x = __float2half(e[2*j]   * inv);
            hv.y = __float2half(e[2*j+1] * inv);
            o2[j] = hv;
        }
    }
    if (tid == 0) ent[blockIdx.x] = m + logf(l) - t * inv;
}

__global__ void ent_reduce(const float* __restrict__ ent, float* __restrict__ out)
{
    __shared__ float red[256];
    const int tid = threadIdx.x;
    float s = 0.f;
    for (int i = tid; i < MS; i += 256) s += ent[i];
    red[tid] = s; __syncthreads();
    #pragma unroll
    for (int k = 128; k > 0; k >>= 1) {
        if (tid < k) red[tid] += red[tid + k];
        __syncthreads();
    }
    if (tid == 0) out[0] = red[0] / (float)MS;
}

// ---------------------------------------------------------------------------
extern "C" void kernel_launch(void* const* d_in, const int* in_sizes, int n_in,
                              void* d_out, int out_size)
{
    const float* x    = (const float*)d_in[0];
    const float* Wq   = (const float*)d_in[1];
    const float* bq   = (const float*)d_in[2];
    const float* Wk   = (const float*)d_in[3];
    const float* bk   = (const float*)d_in[4];
    const float* Wv   = (const float*)d_in[5];
    const float* bv   = (const float*)d_in[6];
    const float* temp = (const float*)d_in[7];
    float* out = (float*)d_out;

    __nv_bfloat16 *xh, *xl, *wqh, *wql, *wkh, *wkl, *mth, *mtl, *yh, *yl;
    __half *xt16, *wvt16, *p16, *z16;
    float *mtp, *p, *cq, *ck, *u, *w, *s0, *ent;
    cudaGetSymbolAddress((void**)&xh,  g_xh);   cudaGetSymbolAddress((void**)&xl,  g_xl);
    cudaGetSymbolAddress((void**)&xt16, g_xt16);
    cudaGetSymbolAddress((void**)&wqh, g_wqh);  cudaGetSymbolAddress((void**)&wql, g_wql);
    cudaGetSymbolAddress((void**)&wkh, g_wkh);  cudaGetSymbolAddress((void**)&wkl, g_wkl);
    cudaGetSymbolAddress((void**)&wvt16, g_wvt16);
    cudaGetSymbolAddress((void**)&mtp, g_mtp);
    cudaGetSymbolAddress((void**)&mth, g_mth);  cudaGetSymbolAddress((void**)&mtl, g_mtl);
    cudaGetSymbolAddress((void**)&yh,  g_yh);   cudaGetSymbolAddress((void**)&yl,  g_yl);
    cudaGetSymbolAddress((void**)&p,   g_p);    cudaGetSymbolAddress((void**)&p16, g_p16);
    cudaGetSymbolAddress((void**)&z16, g_z16);
    cudaGetSymbolAddress((void**)&cq,  g_cq);   cudaGetSymbolAddress((void**)&ck,  g_ck);
    cudaGetSymbolAddress((void**)&u,   g_u);    cudaGetSymbolAddress((void**)&w,   g_w);
    cudaGetSymbolAddress((void**)&s0,  g_s0);   cudaGetSymbolAddress((void**)&ent, g_ent);

    cudaFuncSetAttribute(mma_gemm<0>,    cudaFuncAttributeMaxDynamicSharedMemorySize, SMEMB);
    cudaFuncSetAttribute(mma_gemm<2>,    cudaFuncAttributeMaxDynamicSharedMemorySize, SMEMB);
    cudaFuncSetAttribute(mma_gemm_h1<0>, cudaFuncAttributeMaxDynamicSharedMemorySize, SMEM2);
    cudaFuncSetAttribute(mma_gemm_h1<1>, cudaFuncAttributeMaxDynamicSharedMemorySize, SMEM2);

    dim3 tb(32, 8);

    // 1) fused x prep: xh/xl (bf16 pair) + xt16 (fp16 transposed) in one pass
    split_x_t<<<dim3(DD/32, SS/32, BB), tb>>>(x, xh, xl, xt16);
    // fused weight prep: Wq/Wk splits + Wv transpose in one launch
    prep_w<<<dim3(DD/32, DD/32, 3), tb>>>(Wq, Wk, Wv, wqh, wql, wkh, wkl, wvt16);

    // bias rank-1 terms (exact fp32; zeros in this dataset but handled generally)
    gemv_cqck<<<DD/8, 256>>>(Wq, Wk, bq, bk, cq, ck, s0);
    gemv_uw<<<MS/8, 256>>>(x, cq, ck, u, w);

    // 2) M^T = Wk Wq^T, K-split over 4 partials, then reduce+split to bf16
    mma_gemm<0><<<dim3(DD/128, DD/128, 4), 256, SMEMB>>>(
        wkh, wkl, wqh, wql, mtp, nullptr, nullptr,
        DD, 256, DD, DD, 256, 256, (long)DD*DD);
    mt_reduce_split<<<(DD*DD/4 + 255)/256, 256>>>(mtp, mth, mtl, DD*DD/4);

    // 3) y = x M  (NT vs M^T) -> bf16 hi/lo
    mma_gemm<2><<<dim3(DD/128, MS/128, 1), 256, SMEMB>>>(
        xh, xl, mth, mtl, nullptr, yh, yl,
        DD, DD, DD, DD, 0, 0, 0);

    // 4) scores = y x^T per batch -> fp32
    mma_gemm<0><<<dim3(SS/128, SS/128, BB), 256, SMEMB>>>(
        yh, yl, xh, xl, p, nullptr, nullptr,
        SS, DD, DD, DD, (long)SS*DD, (long)SS*DD, (long)SS*SS);

    // 5) softmax + entropy (adds bias rank-1 terms) -> p16
    softmax_ent<<<MS, 256>>>(p, u, w, s0, p16, ent, temp);

    // 6) z = p x per batch (fp16) -> fp16
    mma_gemm_h1<1><<<dim3(DD/128, SS/128, BB), 256, SMEM2>>>(
        p16, xt16, nullptr, z16, nullptr,
        DD, SS, SS, SS, (long)SS*SS, (long)DD*SS, (long)SS*DD);

    // 7) out = z Wv + bv (fp16 MMA, fp32 out)
    mma_gemm_h1<0><<<dim3(DD/128, MS/128, 1), 256, SMEM2>>>(
        z16, wvt16, out, nullptr, bv,
        DD, DD, DD, DD, 0, 0, 0);

    // 8) entropy mean scalar
    ent_reduce<<<1, 256>>>(ent, out + OUT_ELEMS);
}

// round 17
// speedup vs baseline: 2.6208x; 1.0016x over previous
#include <cuda_runtime.h>
#include <cuda_bf16.h>
#include <cuda_fp16.h>
#include <math.h>
#include <stdint.h>

// Problem dims (fixed)
#define BB 4
#define SS 2048
#define DD 1024
#define MS (BB*SS)          // 8192 rows total
#define OUT_ELEMS (MS*DD)

// --- bf16 split GEMM smem geometry: rows hold hi(64B)|lo(64B), stride 144B ---
#define ROWB   144
#define ATILEB (128*ROWB)
#define STAGEB (2*ATILEB)              // A + B tile = 36864 B
#define NSTAGE 3
#define SMEMB  (NSTAGE*STAGEB)         // 110592 B -> 2 CTAs/SM

// --- fp16 single GEMM smem geometry: rows 64B data + 16B pad -> 80B ---
#define ROWB2   80
#define ATIL2   (128*ROWB2)
#define STAGE2  (2*ATIL2)              // 20480 B
#define SMEM2   (NSTAGE*STAGE2)        // 61440 B

// ---------------------------------------------------------------------------
// PTX helpers (sm_80-level only: cp.async, ldmatrix, mma.sync)
// ---------------------------------------------------------------------------
__device__ __forceinline__ uint32_t smem_u32(const void* p) {
    uint32_t a;
    asm("{ .reg .u64 t; cvta.to.shared.u64 t, %1; cvt.u32.u64 %0, t; }" : "=r"(a) : "l"(p));
    return a;
}
#define CP16(d, s) asm volatile("cp.async.cg.shared.global [%0], [%1], 16;" :: "r"(d), "l"(s))
#define CPCOMMIT() asm volatile("cp.async.commit_group;" ::: "memory")
#define CPWAIT(n)  asm volatile("cp.async.wait_group %0;" :: "n"(n) : "memory")

__device__ __forceinline__ void ldsm4(uint32_t* r, uint32_t a) {
    asm volatile("ldmatrix.sync.aligned.m8n8.x4.shared.b16 {%0,%1,%2,%3}, [%4];"
                 : "=r"(r[0]), "=r"(r[1]), "=r"(r[2]), "=r"(r[3]) : "r"(a));
}
__device__ __forceinline__ void mma16816(float* c, const uint32_t* a, const uint32_t* b) {
    asm volatile("mma.sync.aligned.m16n8k16.row.col.f32.bf16.bf16.f32 "
                 "{%0,%1,%2,%3}, {%4,%5,%6,%7}, {%8,%9}, {%0,%1,%2,%3};"
                 : "+f"(c[0]), "+f"(c[1]), "+f"(c[2]), "+f"(c[3])
                 : "r"(a[0]), "r"(a[1]), "r"(a[2]), "r"(a[3]), "r"(b[0]), "r"(b[1]));
}
__device__ __forceinline__ void mma16816h(float* c, const uint32_t* a, const uint32_t* b) {
    asm volatile("mma.sync.aligned.m16n8k16.row.col.f32.f16.f16.f32 "
                 "{%0,%1,%2,%3}, {%4,%5,%6,%7}, {%8,%9}, {%0,%1,%2,%3};"
                 : "+f"(c[0]), "+f"(c[1]), "+f"(c[2]), "+f"(c[3])
                 : "r"(a[0]), "r"(a[1]), "r"(a[2]), "r"(a[3]), "r"(b[0]), "r"(b[1]));
}

// ---------------------------------------------------------------------------
// Static scratch (allocation-free rule)
// ---------------------------------------------------------------------------
__device__ __align__(256) __nv_bfloat16 g_xh[MS*DD], g_xl[MS*DD];
__device__ __align__(256) __half         g_xt16[MS*DD];                 // per-batch x^T fp16
__device__ __align__(256) __nv_bfloat16 g_wqh[DD*DD], g_wql[DD*DD];
__device__ __align__(256) __nv_bfloat16 g_wkh[DD*DD], g_wkl[DD*DD];
__device__ __align__(256) __half         g_wvt16[DD*DD];                 // Wv^T fp16
__device__ __align__(256) float          g_mtp[4*DD*DD];                 // M^T K-split partials
__device__ __align__(256) __nv_bfloat16 g_mth[DD*DD], g_mtl[DD*DD];     // M^T = Wk Wq^T
__device__ __align__(256) __nv_bfloat16 g_yh[MS*DD], g_yl[MS*DD];       // y = x M
__device__ __align__(256) float          g_p[(size_t)BB*SS*SS];
__device__ __align__(256) __half         g_p16[(size_t)BB*SS*SS];
__device__ __align__(256) __half         g_z16[MS*DD];                   // z = p x
__device__ __align__(256) float          g_cq[DD], g_ck[DD], g_u[MS], g_w[MS], g_s0[1];
__device__ __align__(256) float          g_ent[MS];

// ---------------------------------------------------------------------------
// bf16 split GEMM via mma.sync:
//   C[M,N] = (Ah+Al)[.,K] x (Bh+Bl)[.,K]^T   (3 MMAs: hh + hl + lh)
// CTA tile 128x128, K-chunk 32, 256 threads = 8 warps (4 M x 2 N),
// 3-stage cp.async ring, ONE barrier/chunk, 2 CTAs/SM.
// EPI 0: fp32 store.  EPI 2: bf16 hi/lo split store (Oh/Ol, row stride N).
// ---------------------------------------------------------------------------
template<int EPI>
__global__ __launch_bounds__(256, 2)
void mma_gemm(const __nv_bfloat16* __restrict__ Ah, const __nv_bfloat16* __restrict__ Al,
              const __nv_bfloat16* __restrict__ Bh, const __nv_bfloat16* __restrict__ Bl,
              float* __restrict__ Cf, __nv_bfloat16* __restrict__ Oh, __nv_bfloat16* __restrict__ Ol,
              int N, int K, int lda, int ldb, long sA, long sB, long sC)
{
    extern __shared__ char sm[];
    const uint32_t sb = smem_u32(sm);
    const int tid = threadIdx.x, lane = tid & 31, warp = tid >> 5;
    const int wm = warp & 3, wn = warp >> 2;     // 4 M-warps x 2 N-warps
    const int bz = blockIdx.z;

    const __nv_bfloat16* srcA[2] = {
        Ah + (long)bz * sA + (long)blockIdx.y * 128 * lda,
        Al + (long)bz * sA + (long)blockIdx.y * 128 * lda };
    const __nv_bfloat16* srcB[2] = {
        Bh + (long)bz * sB + (long)blockIdx.x * 128 * ldb,
        Bl + (long)bz * sB + (long)blockIdx.x * 128 * ldb };

    float acc[2][8][4];
    #pragma unroll
    for (int a = 0; a < 2; a++)
        #pragma unroll
        for (int b = 0; b < 8; b++)
            #pragma unroll
            for (int c = 0; c < 4; c++) acc[a][b][c] = 0.f;

    const int NC = K >> 5;

    auto load_stage = [&](int c) {
        const uint32_t dstS = sb + (uint32_t)(c % NSTAGE) * STAGEB;
        const long kof = (long)c * 32;
        #pragma unroll
        for (int p = 0; p < 4; p++) {
            const int u = tid + p * 256;
            const int r = u >> 3, seg = u & 7;
            const int hl = seg >> 2;
            const long so = kof + (seg & 3) * 8;
            CP16(dstS + r * ROWB + seg * 16,          srcA[hl] + (long)r * lda + so);
            CP16(dstS + ATILEB + r * ROWB + seg * 16, srcB[hl] + (long)r * ldb + so);
        }
        CPCOMMIT();
    };

    load_stage(0);
    if (NC > 1) load_stage(1);

    for (int c = 0; c < NC; c++) {
        if (c + 2 <= NC) { CPWAIT(1); } else { CPWAIT(0); }
        __syncthreads();
        if (c + 2 < NC) load_stage(c + 2);

        const uint32_t stb = sb + (uint32_t)(c % NSTAGE) * STAGEB;
        #pragma unroll
        for (int ks = 0; ks < 2; ks++) {
            uint32_t aHi[2][4], aLo[2][4];
            const int rA   = wm * 32 + (lane & 15);
            const int colA = ks * 32 + ((lane >> 4) << 4);
            #pragma unroll
            for (int mf = 0; mf < 2; mf++) {
                const uint32_t ad = stb + (rA + mf * 16) * ROWB + colA;
                ldsm4(aHi[mf], ad);
                ldsm4(aLo[mf], ad + 64);
            }
            const int rB   = wn * 64 + ((lane >> 4) & 1) * 8 + (lane & 7);
            const int colB = ks * 32 + ((lane >> 3) & 1) * 16;
            #pragma unroll
            for (int g = 0; g < 4; g++) {
                uint32_t bh4[4], bl4[4];
                const uint32_t bd = stb + ATILEB + (rB + g * 16) * ROWB + colB;
                ldsm4(bh4, bd);
                ldsm4(bl4, bd + 64);
                #pragma unroll
                for (int mf = 0; mf < 2; mf++) {
                    mma16816(acc[mf][2*g],   aHi[mf], bh4);
                    mma16816(acc[mf][2*g],   aHi[mf], bl4);
                    mma16816(acc[mf][2*g],   aLo[mf], bh4);
                    mma16816(acc[mf][2*g+1], aHi[mf], bh4 + 2);
                    mma16816(acc[mf][2*g+1], aHi[mf], bl4 + 2);
                    mma16816(acc[mf][2*g+1], aLo[mf], bh4 + 2);
                }
            }
        }
    }

    // ---- epilogue ----
    const long rbase = (long)blockIdx.y * 128 + wm * 32 + (lane >> 2);
    const int  gcol0 = blockIdx.x * 128;

    #pragma unroll
    for (int mf = 0; mf < 2; mf++)
        #pragma unroll
        for (int rh = 0; rh < 2; rh++) {
            const long r = rbase + mf * 16 + rh * 8;
            #pragma unroll
            for (int nf = 0; nf < 8; nf++) {
                const int col = gcol0 + wn * 64 + 2 * (lane & 3) + nf * 8;
                float v0 = acc[mf][nf][rh * 2 + 0];
                float v1 = acc[mf][nf][rh * 2 + 1];
                if (EPI == 0) {
                    float2 f2; f2.x = v0; f2.y = v1;
                    *(float2*)(Cf + (long)bz * sC + r * N + col) = f2;
                } else {
                    __nv_bfloat16 h0 = __float2bfloat16(v0);
                    __nv_bfloat16 h1 = __float2bfloat16(v1);
                    __nv_bfloat162 hh; hh.x = h0; hh.y = h1;
                    __nv_bfloat162 ll;
                    ll.x = __float2bfloat16(v0 - __bfloat162float(h0));
                    ll.y = __float2bfloat16(v1 - __bfloat162float(h1));
                    *(__nv_bfloat162*)(Oh + (long)bz * sC + r * N + col) = hh;
                    *(__nv_bfloat162*)(Ol + (long)bz * sC + r * N + col) = ll;
                }
            }
        }
}

// ---------------------------------------------------------------------------
// fp16 single-term GEMM: C[M,N] = A[.,K] x B[.,K]^T, fp32 accum.
// EPI 0: fp32 store + bias.  EPI 1: fp16 store.
// ---------------------------------------------------------------------------
template<int EPI>
__global__ __launch_bounds__(256, 2)
void mma_gemm_h1(const __half* __restrict__ A, const __half* __restrict__ B,
                 float* __restrict__ Cf, __half* __restrict__ Oz,
                 const float* __restrict__ bias,
                 int N, int K, int lda, int ldb, long sA, long sB, long sC)
{
    extern __shared__ char sm[];
    const uint32_t sb = smem_u32(sm);
    const int tid = threadIdx.x, lane = tid & 31, warp = tid >> 5;
    const int wm = warp & 3, wn = warp >> 2;
    const int bz = blockIdx.z;

    const __half* srcA = A + (long)bz * sA + (long)blockIdx.y * 128 * lda;
    const __half* srcB = B + (long)bz * sB + (long)blockIdx.x * 128 * ldb;

    float acc[2][8][4];
    #pragma unroll
    for (int a = 0; a < 2; a++)
        #pragma unroll
        for (int b = 0; b < 8; b++)
            #pragma unroll
            for (int c = 0; c < 4; c++) acc[a][b][c] = 0.f;

    const int NC = K >> 5;

    auto load_stage = [&](int c) {
        const uint32_t dstS = sb + (uint32_t)(c % NSTAGE) * STAGE2;
        const long kof = (long)c * 32;
        #pragma unroll
        for (int p = 0; p < 2; p++) {
            const int u = tid + p * 256;
            const int r = u >> 2, s = u & 3;
            const long so = kof + s * 8;
            CP16(dstS + r * ROWB2 + s * 16,         srcA + (long)r * lda + so);
            CP16(dstS + ATIL2 + r * ROWB2 + s * 16, srcB + (long)r * ldb + so);
        }
        CPCOMMIT();
    };

    load_stage(0);
    if (NC > 1) load_stage(1);

    for (int c = 0; c < NC; c++) {
        if (c + 2 <= NC) { CPWAIT(1); } else { CPWAIT(0); }
        __syncthreads();
        if (c + 2 < NC) load_stage(c + 2);

        const uint32_t stb = sb + (uint32_t)(c % NSTAGE) * STAGE2;
        #pragma unroll
        for (int ks = 0; ks < 2; ks++) {
            uint32_t aF[2][4];
            const int rA   = wm * 32 + (lane & 15);
            const int colA = ks * 32 + ((lane >> 4) << 4);
            #pragma unroll
            for (int mf = 0; mf < 2; mf++)
                ldsm4(aF[mf], stb + (rA + mf * 16) * ROWB2 + colA);
            const int rB   = wn * 64 + ((lane >> 4) & 1) * 8 + (lane & 7);
            const int colB = ks * 32 + ((lane >> 3) & 1) * 16;
            #pragma unroll
            for (int g = 0; g < 4; g++) {
                uint32_t b4[4];
                ldsm4(b4, stb + ATIL2 + (rB + g * 16) * ROWB2 + colB);
                #pragma unroll
                for (int mf = 0; mf < 2; mf++) {
                    mma16816h(acc[mf][2*g],   aF[mf], b4);
                    mma16816h(acc[mf][2*g+1], aF[mf], b4 + 2);
                }
            }
        }
    }

    const long rbase = (long)blockIdx.y * 128 + wm * 32 + (lane >> 2);
    const int  gcol0 = blockIdx.x * 128;
    #pragma unroll
    for (int mf = 0; mf < 2; mf++)
        #pragma unroll
        for (int rh = 0; rh < 2; rh++) {
            const long r = rbase + mf * 16 + rh * 8;
            #pragma unroll
            for (int nf = 0; nf < 8; nf++) {
                const int col = gcol0 + wn * 64 + 2 * (lane & 3) + nf * 8;
                float v0 = acc[mf][nf][rh * 2 + 0];
                float v1 = acc[mf][nf][rh * 2 + 1];
                if (EPI == 0) {
                    if (bias) { v0 += bias[col]; v1 += bias[col + 1]; }
                    float2 f2; f2.x = v0; f2.y = v1;
                    *(float2*)(Cf + (long)bz * sC + r * N + col) = f2;
                } else {
                    __half2 hv; hv.x = __float2half(v0); hv.y = __float2half(v1);
                    *(__half2*)(Oz + (long)bz * sC + r * N + col) = hv;
                }
            }
        }
}

// ---------------------------------------------------------------------------
// Fused x prep: per batch, tile-transpose kernel that emits
//   xh/xl (bf16 hi/lo, [S,D] layout, coalesced) AND xt16 (fp16, [D,S] layout)
// grid (DD/32, SS/32, BB), block (32,8)
// ---------------------------------------------------------------------------
__global__ void split_x_t(const float* __restrict__ in,
                          __nv_bfloat16* __restrict__ oh, __nv_bfloat16* __restrict__ ol,
                          __half* __restrict__ ot)
{
    __shared__ float t[32][33];
    const long bIn = (long)blockIdx.z * SS * DD;
    const long bOt = (long)blockIdx.z * DD * SS;
    const int c0 = blockIdx.x * 32, rr0 = blockIdx.y * 32;
    const int tx = threadIdx.x, ty = threadIdx.y;
    #pragma unroll
    for (int k = 0; k < 32; k += 8) {
        const long idx = bIn + (long)(rr0 + ty + k) * DD + c0 + tx;
        float v = in[idx];
        t[ty + k][tx] = v;
        __nv_bfloat16 h = __float2bfloat16(v);
        oh[idx] = h;
        ol[idx] = __float2bfloat16(v - __bfloat162float(h));
    }
    __syncthreads();
    #pragma unroll
    for (int k = 0; k < 32; k += 8)
        ot[bOt + (long)(c0 + ty + k) * SS + rr0 + tx] = __float2half(t[tx][ty + k]);
}

// ---------------------------------------------------------------------------
// Fused weight prep. grid (32, 32, 3), block (32,8):
//   z=0: Wq elementwise bf16 hi/lo split (tile region)
//   z=1: Wk elementwise bf16 hi/lo split
//   z=2: Wv transpose -> fp16 Wv^T
// ---------------------------------------------------------------------------
__global__ void prep_w(const float* __restrict__ Wq, const float* __restrict__ Wk,
                       const float* __restrict__ Wv,
                       __nv_bfloat16* __restrict__ qh, __nv_bfloat16* __restrict__ ql,
                       __nv_bfloat16* __restrict__ kh, __nv_bfloat16* __restrict__ kl,
                       __half* __restrict__ wvt)
{
    const int c0 = blockIdx.x * 32, rr0 = blockIdx.y * 32;
    const int tx = threadIdx.x, ty = threadIdx.y;
    if (blockIdx.z < 2) {
        const float* in = blockIdx.z ? Wk : Wq;
        __nv_bfloat16* oh = blockIdx.z ? kh : qh;
        __nv_bfloat16* ol = blockIdx.z ? kl : ql;
        #pragma unroll
        for (int k = 0; k < 32; k += 8) {
            const long idx = (long)(rr0 + ty + k) * DD + c0 + tx;
            float v = in[idx];
            __nv_bfloat16 h = __float2bfloat16(v);
            oh[idx] = h;
            ol[idx] = __float2bfloat16(v - __bfloat162float(h));
        }
    } else {
        __shared__ float t[32][33];
        #pragma unroll
        for (int k = 0; k < 32; k += 8)
            t[ty + k][tx] = Wv[(long)(rr0 + ty + k) * DD + c0 + tx];
        __syncthreads();
        #pragma unroll
        for (int k = 0; k < 32; k += 8)
            wvt[(long)(c0 + ty + k) * DD + rr0 + tx] = __float2half(t[tx][ty + k]);
    }
}

// MT partials (4) -> sum -> bf16 hi/lo
__global__ void mt_reduce_split(const float* __restrict__ parts, __nv_bfloat16* __restrict__ oh,
                                __nv_bfloat16* __restrict__ ol, int n4)
{
    int i = blockIdx.x * 256 + threadIdx.x;
    if (i < n4) {
        float4 s = ((const float4*)parts)[i];
        #pragma unroll
        for (int p = 1; p < 4; p++) {
            float4 t = ((const float4*)(parts + (size_t)p * DD * DD))[i];
            s.x += t.x; s.y += t.y; s.z += t.z; s.w += t.w;
        }
        __nv_bfloat16 h0 = __float2bfloat16(s.x), h1 = __float2bfloat16(s.y);
        __nv_bfloat16 h2 = __float2bfloat16(s.z), h3 = __float2bfloat16(s.w);
        __nv_bfloat162 hA; hA.x = h0; hA.y = h1;
        __nv_bfloat162 hB; hB.x = h2; hB.y = h3;
        __nv_bfloat162 lA, lB;
        lA.x = __float2bfloat16(s.x - __bfloat162float(h0));
        lA.y = __float2bfloat16(s.y - __bfloat162float(h1));
        lB.x = __float2bfloat16(s.z - __bfloat162float(h2));
        lB.y = __float2bfloat16(s.w - __bfloat162float(h3));
        ((__nv_bfloat162*)oh)[2*i]   = hA;
        ((__nv_bfloat162*)oh)[2*i+1] = hB;
        ((__nv_bfloat162*)ol)[2*i]   = lA;
        ((__nv_bfloat162*)ol)[2*i+1] = lB;
    }
}

// cq = Wq bk, ck = Wk bq (warp per output element, float4 loads);
// block 0 warp 0 also s0 = bq . bk
__global__ void gemv_cqck(const float* __restrict__ Wq, const float* __restrict__ Wk,
                          const float* __restrict__ bq, const float* __restrict__ bk,
                          float* __restrict__ cq, float* __restrict__ ck,
                          float* __restrict__ s0)
{
    const int lane = threadIdx.x & 31, warp = threadIdx.x >> 5;
    const int d = blockIdx.x * 8 + warp;
    const float4* wq4 = (const float4*)(Wq + (long)d * DD);
    const float4* wk4 = (const float4*)(Wk + (long)d * DD);
    const float4* bq4 = (const float4*)bq;
    const float4* bk4 = (const float4*)bk;
    float a1 = 0.f, a2 = 0.f;
    #pragma unroll
    for (int k = 0; k < DD/4; k += 32) {
        float4 q = wq4[lane + k], kk = wk4[lane + k];
        float4 vq = bq4[lane + k], vk = bk4[lane + k];
        a1 += q.x*vk.x + q.y*vk.y + q.z*vk.z + q.w*vk.w;
        a2 += kk.x*vq.x + kk.y*vq.y + kk.z*vq.z + kk.w*vq.w;
    }
    #pragma unroll
    for (int o = 16; o > 0; o >>= 1) {
        a1 += __shfl_xor_sync(0xffffffff, a1, o);
        a2 += __shfl_xor_sync(0xffffffff, a2, o);
    }
    if (lane == 0) { cq[d] = a1; ck[d] = a2; }
    if (blockIdx.x == 0 && warp == 0) {
        float s = 0.f;
        #pragma unroll
        for (int k = 0; k < DD/4; k += 32) {
            float4 vq = bq4[lane + k], vk = bk4[lane + k];
            s += vq.x*vk.x + vq.y*vk.y + vq.z*vk.z + vq.w*vk.w;
        }
        #pragma unroll
        for (int o = 16; o > 0; o >>= 1) s += __shfl_xor_sync(0xffffffff, s, o);
        if (lane == 0) s0[0] = s;
    }
}

// u = x cq, w = x ck (warp per row, float4 loads: warp reads 512B/iter)
__global__ void gemv_uw(const float* __restrict__ x, const float* __restrict__ cq,
                        const float* __restrict__ ck, float* __restrict__ u, float* __restrict__ w)
{
    const int lane = threadIdx.x & 31, warp = threadIdx.x >> 5;
    const long r = (long)blockIdx.x * 8 + warp;
    const float4* x4  = (const float4*)(x + r * DD);
    const float4* cq4 = (const float4*)cq;
    const float4* ck4 = (const float4*)ck;
    float a1 = 0.f, a2 = 0.f;
    #pragma unroll
    for (int k = 0; k < DD/4; k += 32) {
        float4 xv = x4[lane + k];
        float4 q = cq4[lane + k];
        float4 c = ck4[lane + k];
        a1 += xv.x*q.x + xv.y*q.y + xv.z*q.z + xv.w*q.w;
        a2 += xv.x*c.x + xv.y*c.y + xv.z*c.z + xv.w*c.w;
    }
    #pragma unroll
    for (int o = 16; o > 0; o >>= 1) {
        a1 += __shfl_xor_sync(0xffffffff, a1, o);
        a2 += __shfl_xor_sync(0xffffffff, a2, o);
    }
    if (lane == 0) { u[r] = a1; w[r] = a2; }
}

// ---------------------------------------------------------------------------
// Row softmax + entropy; logits = (raw + u_r + w_c + s0)/(8*temp); probs fp16.
// float4 vectorized, warp-shuffle reductions, fused (l,t) cross-warp stage.
// ---------------------------------------------------------------------------
__global__ void softmax_ent(const float* __restrict__ P, const float* __restrict__ u,
                            const float* __restrict__ w, const float* __restrict__ s0,
                            __half* __restrict__ P16, float* __restrict__ ent,
                            const float* __restrict__ temp)
{
    __shared__ float sred[20];
    const float* p = P + (long)blockIdx.x * SS;
    __half* o = P16 + (long)blockIdx.x * SS;
    const int tid = threadIdx.x, lane = tid & 31, wid = tid >> 5;
    const float scale = 1.0f / (8.0f * temp[0]);
    const float ub = u[blockIdx.x] + s0[0];
    const float* wb = w + (blockIdx.x / SS) * SS;

    float v[8];
    {
        const int c8 = tid * 8;
        float4 p0 = ((const float4*)(p + c8))[0];
        float4 p1 = ((const float4*)(p + c8))[1];
        float4 w0 = ((const float4*)(wb + c8))[0];
        float4 w1 = ((const float4*)(wb + c8))[1];
        v[0] = (p0.x + ub + w0.x) * scale;
        v[1] = (p0.y + ub + w0.y) * scale;
        v[2] = (p0.z + ub + w0.z) * scale;
        v[3] = (p0.w + ub + w0.w) * scale;
        v[4] = (p1.x + ub + w1.x) * scale;
        v[5] = (p1.y + ub + w1.y) * scale;
        v[6] = (p1.z + ub + w1.z) * scale;
        v[7] = (p1.w + ub + w1.w) * scale;
    }

    float m = v[0];
    #pragma unroll
    for (int j = 1; j < 8; j++) m = fmaxf(m, v[j]);
    #pragma unroll
    for (int s = 16; s > 0; s >>= 1) m = fmaxf(m, __shfl_xor_sync(0xffffffff, m, s));
    if (lane == 0) sred[wid] = m;
    __syncthreads();
    if (wid == 0) {
        float t2 = (lane < 8) ? sred[lane] : -3.4e38f;
        #pragma unroll
        for (int s = 4; s > 0; s >>= 1) t2 = fmaxf(t2, __shfl_xor_sync(0xffffffff, t2, s));
        if (lane == 0) sred[16] = t2;
    }
    __syncthreads();
    m = sred[16];

    float e[8], l = 0.f, t = 0.f;
    #pragma unroll
    for (int j = 0; j < 8; j++) {
        e[j] = __expf(v[j] - m);
        l += e[j];
        t += e[j] * v[j];
    }
    #pragma unroll
    for (int s = 16; s > 0; s >>= 1) {
        l += __shfl_xor_sync(0xffffffff, l, s);
        t += __shfl_xor_sync(0xffffffff, t, s);
    }
    if (lane == 0) { sred[wid] = l; sred[8 + wid] = t; }
    __syncthreads();
    if (wid == 0) {
        float a = (lane < 8) ? sred[lane] : 0.f;
        float b = (lane < 8) ? sred[8 + lane] : 0.f;
        #pragma unroll
        for (int s = 4; s > 0; s >>= 1) {
            a += __shfl_xor_sync(0xffffffff, a, s);
            b += __shfl_xor_sync(0xffffffff, b, s);
        }
        if (lane == 0) { sred[17] = a; sred[18] = b; }
    }
    __syncthreads();
    l = sred[17]; t = sred[18];

    const float inv = 1.0f / l;
    {
        __half2* o2 = (__half2*)(o + tid * 8);
        #pragma unroll
        for (int j = 0; j < 4; j++) {
            __half2 hv;
            hv.x = __float2half(e[2*j]   * inv);
            hv.y = __float2half(e[2*j+1] * inv);
            o2[j] = hv;
        }
    }
    if (tid == 0) ent[blockIdx.x] = m + logf(l) - t * inv;
}

__global__ void ent_reduce(const float* __restrict__ ent, float* __restrict__ out)
{
    __shared__ float red[256];
    const int tid = threadIdx.x;
    float s = 0.f;
    for (int i = tid; i < MS; i += 256) s += ent[i];
    red[tid] = s; __syncthreads();
    #pragma unroll
    for (int k = 128; k > 0; k >>= 1) {
        if (tid < k) red[tid] += red[tid + k];
        __syncthreads();
    }
    if (tid == 0) out[0] = red[0] / (float)MS;
}

// ---------------------------------------------------------------------------
extern "C" void kernel_launch(void* const* d_in, const int* in_sizes, int n_in,
                              void* d_out, int out_size)
{
    const float* x    = (const float*)d_in[0];
    const float* Wq   = (const float*)d_in[1];
    const float* bq   = (const float*)d_in[2];
    const float* Wk   = (const float*)d_in[3];
    const float* bk   = (const float*)d_in[4];
    const float* Wv   = (const float*)d_in[5];
    const float* bv   = (const float*)d_in[6];
    const float* temp = (const float*)d_in[7];
    float* out = (float*)d_out;

    __nv_bfloat16 *xh, *xl, *wqh, *wql, *wkh, *wkl, *mth, *mtl, *yh, *yl;
    __half *xt16, *wvt16, *p16, *z16;
    float *mtp, *p, *cq, *ck, *u, *w, *s0, *ent;
    cudaGetSymbolAddress((void**)&xh,  g_xh);   cudaGetSymbolAddress((void**)&xl,  g_xl);
    cudaGetSymbolAddress((void**)&xt16, g_xt16);
    cudaGetSymbolAddress((void**)&wqh, g_wqh);  cudaGetSymbolAddress((void**)&wql, g_wql);
    cudaGetSymbolAddress((void**)&wkh, g_wkh);  cudaGetSymbolAddress((void**)&wkl, g_wkl);
    cudaGetSymbolAddress((void**)&wvt16, g_wvt16);
    cudaGetSymbolAddress((void**)&mtp, g_mtp);
    cudaGetSymbolAddress((void**)&mth, g_mth);  cudaGetSymbolAddress((void**)&mtl, g_mtl);
    cudaGetSymbolAddress((void**)&yh,  g_yh);   cudaGetSymbolAddress((void**)&yl,  g_yl);
    cudaGetSymbolAddress((void**)&p,   g_p);    cudaGetSymbolAddress((void**)&p16, g_p16);
    cudaGetSymbolAddress((void**)&z16, g_z16);
    cudaGetSymbolAddress((void**)&cq,  g_cq);   cudaGetSymbolAddress((void**)&ck,  g_ck);
    cudaGetSymbolAddress((void**)&u,   g_u);    cudaGetSymbolAddress((void**)&w,   g_w);
    cudaGetSymbolAddress((void**)&s0,  g_s0);   cudaGetSymbolAddress((void**)&ent, g_ent);

    cudaFuncSetAttribute(mma_gemm<0>,    cudaFuncAttributeMaxDynamicSharedMemorySize, SMEMB);
    cudaFuncSetAttribute(mma_gemm<2>,    cudaFuncAttributeMaxDynamicSharedMemorySize, SMEMB);
    cudaFuncSetAttribute(mma_gemm_h1<0>, cudaFuncAttributeMaxDynamicSharedMemorySize, SMEM2);
    cudaFuncSetAttribute(mma_gemm_h1<1>, cudaFuncAttributeMaxDynamicSharedMemorySize, SMEM2);

    dim3 tb(32, 8);

    // 1) fused x prep: xh/xl (bf16 pair) + xt16 (fp16 transposed) in one pass
    split_x_t<<<dim3(DD/32, SS/32, BB), tb>>>(x, xh, xl, xt16);
    // fused weight prep: Wq/Wk splits + Wv transpose in one launch
    prep_w<<<dim3(DD/32, DD/32, 3), tb>>>(Wq, Wk, Wv, wqh, wql, wkh, wkl, wvt16);

    // bias rank-1 terms (exact fp32; zeros in this dataset but handled generally)
    gemv_cqck<<<DD/8, 256>>>(Wq, Wk, bq, bk, cq, ck, s0);
    gemv_uw<<<MS/8, 256>>>(x, cq, ck, u, w);

    // 2) M^T = Wk Wq^T, K-split over 4 partials, then reduce+split to bf16
    mma_gemm<0><<<dim3(DD/128, DD/128, 4), 256, SMEMB>>>(
        wkh, wkl, wqh, wql, mtp, nullptr, nullptr,
        DD, 256, DD, DD, 256, 256, (long)DD*DD);
    mt_reduce_split<<<(DD*DD/4 + 255)/256, 256>>>(mtp, mth, mtl, DD*DD/4);

    // 3) y = x M  (NT vs M^T) -> bf16 hi/lo
    mma_gemm<2><<<dim3(DD/128, MS/128, 1), 256, SMEMB>>>(
        xh, xl, mth, mtl, nullptr, yh, yl,
        DD, DD, DD, DD, 0, 0, 0);

    // 4) scores = y x^T per batch -> fp32
    mma_gemm<0><<<dim3(SS/128, SS/128, BB), 256, SMEMB>>>(
        yh, yl, xh, xl, p, nullptr, nullptr,
        SS, DD, DD, DD, (long)SS*DD, (long)SS*DD, (long)SS*SS);

    // 5) softmax + entropy (adds bias rank-1 terms) -> p16
    softmax_ent<<<MS, 256>>>(p, u, w, s0, p16, ent, temp);

    // 6) z = p x per batch (fp16) -> fp16
    mma_gemm_h1<1><<<dim3(DD/128, SS/128, BB), 256, SMEM2>>>(
        p16, xt16, nullptr, z16, nullptr,
        DD, SS, SS, SS, (long)SS*SS, (long)DD*SS, (long)SS*DD);

    // 7) out = z Wv + bv (fp16 MMA, fp32 out)
    mma_gemm_h1<0><<<dim3(DD/128, MS/128, 1), 256, SMEM2>>>(
        z16, wvt16, out, nullptr, bv,
        DD, DD, DD, DD, 0, 0, 0);

    // 8) entropy mean scalar
    ent_reduce<<<1, 256>>>(ent, out + OUT_ELEMS);
}